// round 8
// baseline (speedup 1.0000x reference)
#include <cuda_runtime.h>
#include <cuda_bf16.h>
#include <cstdint>
#include <math.h>

#define NB  4
#define NT  2048
#define NC  1024
#define NHH 16
#define HD  64
#define HP  32   // HD/2 packed u32 per row

// Device-global scratch (no cudaMalloc allowed)
__device__ uint32_t g_qh[(size_t)NB * NHH * NT * HP];
__device__ uint32_t g_ql[(size_t)NB * NHH * NT * HP];
__device__ uint32_t g_kh[(size_t)NB * NHH * NT * HP];
__device__ uint32_t g_kl[(size_t)NB * NHH * NT * HP];
__device__ uint32_t g_vh[(size_t)NB * NHH * NT * HP];
__device__ uint32_t g_vl[(size_t)NB * NHH * NT * HP];
__device__ float    g_y [(size_t)NB * NT * NC];

// ============================ helpers ============================
__device__ __forceinline__ uint32_t pack_bf16(float a, float b) {
    __nv_bfloat162 t = __floats2bfloat162_rn(a, b);
    return *(uint32_t*)&t;
}
__device__ __forceinline__ void split2(float x, float& hi, float& lo) {
    __nv_bfloat16 h = __float2bfloat16(x);
    hi = __bfloat162float(h);
    lo = x - hi;
}
__device__ __forceinline__ void mma_bf16(float* d, const uint32_t* a, const uint32_t* b) {
    asm volatile(
        "mma.sync.aligned.m16n8k16.row.col.f32.bf16.bf16.f32 "
        "{%0,%1,%2,%3}, {%4,%5,%6,%7}, {%8,%9}, {%0,%1,%2,%3};"
        : "+f"(d[0]), "+f"(d[1]), "+f"(d[2]), "+f"(d[3])
        : "r"(a[0]), "r"(a[1]), "r"(a[2]), "r"(a[3]), "r"(b[0]), "r"(b[1]));
}
__device__ __forceinline__ uint32_t smem_u32(const void* p) {
    uint32_t a;
    asm("{ .reg .u64 t; cvta.to.shared.u64 t, %1; cvt.u32.u64 %0, t; }"
        : "=r"(a) : "l"(p));
    return a;
}
__device__ __forceinline__ void ldsm_x4(uint32_t* r, uint32_t addr) {
    asm volatile("ldmatrix.sync.aligned.m8n8.x4.shared.b16 {%0,%1,%2,%3}, [%4];"
        : "=r"(r[0]), "=r"(r[1]), "=r"(r[2]), "=r"(r[3]) : "r"(addr));
}

// ===================== bf16x3 split mma.sync GEMM (pipelined + LDSM) =====================
static constexpr int BM = 128, BN = 128, BK = 32;
static constexpr int KTOT = 1024, NCHUNK = KTOT / BK;
static constexpr int LDP = 20;
// stage layout (bytes): As_hi 0 | As_lo 10240 | Bs_hi 20480 | Bs_lo 30720
static constexpr int G_STG = 10240;                   // u32 per stage
static constexpr int G_SMEM_BYTES = 2 * G_STG * 4;    // 81920

template <int MODE, int NGLOB>
__global__ __launch_bounds__(256) void gemm_bf16_kernel(
    const float* __restrict__ A, const float* __restrict__ W,
    const float* __restrict__ bias, float* __restrict__ out)
{
    extern __shared__ uint32_t dsm[];

    const int tid  = threadIdx.x;
    const int warp = tid >> 5, lane = tid & 31;
    const int g = lane >> 2, tq = lane & 3;
    const int wm = (warp >> 2) * 64;
    const int wn = (warp & 3) * 32;
    const int m0 = blockIdx.y * BM, n0 = blockIdx.x * BN;
    const float* __restrict__ Ap = (MODE == 0) ? A : (const float*)g_y;
    const uint32_t dsm_b = smem_u32(dsm);

    const int sn = tid & 127;
    const int pbase = (tid >> 7) * 8;

    // ldmatrix lane->row mapping
    const int arow_f = ((lane >> 3) & 1) * 8 + (lane & 7);  // A: row within m16 tile
    const int akp    = (lane >> 4) * 4;                     // A: kp sub-block
    const int brow_f = (lane >> 4) * 8 + (lane & 7);        // B: col within fn-pair
    const int bkp    = ((lane >> 3) & 1) * 4;               // B: kp sub-block

    float4 pa[4];
    float  pb[16];

    auto ldg_chunk = [&](int ci) {
        const int k0 = ci * BK;
#pragma unroll
        for (int it = 0; it < 4; it++) {
            int s = tid + it * 256;
            int row = s >> 3, q = s & 7;
            pa[it] = *(const float4*)(Ap + (size_t)(m0 + row) * KTOT + k0 + q * 4);
        }
        const float* wp = W + (size_t)(k0 + pbase * 2) * NGLOB + n0 + sn;
#pragma unroll
        for (int j = 0; j < 8; j++) {
            pb[2 * j]     = wp[0];
            pb[2 * j + 1] = wp[NGLOB];
            wp += 2 * (size_t)NGLOB;
        }
    };
    auto sts_chunk = [&](uint32_t* st) {
        uint32_t* As_hi = st;
        uint32_t* As_lo = st + 2560;
        uint32_t* Bs_hi = st + 5120;
        uint32_t* Bs_lo = st + 7680;
#pragma unroll
        for (int it = 0; it < 4; it++) {
            int s = tid + it * 256;
            int row = s >> 3, q = s & 7;
            float h0, l0, h1, l1, h2, l2, h3, l3;
            split2(pa[it].x, h0, l0); split2(pa[it].y, h1, l1);
            split2(pa[it].z, h2, l2); split2(pa[it].w, h3, l3);
            int o = row * LDP + q * 2;
            As_hi[o]     = pack_bf16(h0, h1);
            As_hi[o + 1] = pack_bf16(h2, h3);
            As_lo[o]     = pack_bf16(l0, l1);
            As_lo[o + 1] = pack_bf16(l2, l3);
        }
#pragma unroll
        for (int j = 0; j < 8; j++) {
            float h0, l0, h1, l1;
            split2(pb[2 * j], h0, l0); split2(pb[2 * j + 1], h1, l1);
            Bs_hi[sn * LDP + pbase + j] = pack_bf16(h0, h1);
            Bs_lo[sn * LDP + pbase + j] = pack_bf16(l0, l1);
        }
    };

    float acc[4][4][4] = {};

    ldg_chunk(0);
    sts_chunk(dsm);
    __syncthreads();

    for (int ci = 0; ci < NCHUNK; ci++) {
        if (ci + 1 < NCHUNK) ldg_chunk(ci + 1);

        const uint32_t stb = dsm_b + (ci & 1) * (G_STG * 4);
#pragma unroll
        for (int ks = 0; ks < 2; ks++) {
            uint32_t ah[4][4], al[4][4];
#pragma unroll
            for (int fm = 0; fm < 4; fm++) {
                uint32_t off = ((wm + fm * 16 + arow_f) * LDP + ks * 8 + akp) * 4;
                ldsm_x4(ah[fm], stb + off);
                ldsm_x4(al[fm], stb + 10240 + off);
            }
            uint32_t bhp[2][4], blp[2][4];
#pragma unroll
            for (int fnp = 0; fnp < 2; fnp++) {
                uint32_t off = ((wn + fnp * 16 + brow_f) * LDP + ks * 8 + bkp) * 4;
                ldsm_x4(bhp[fnp], stb + 20480 + off);
                ldsm_x4(blp[fnp], stb + 30720 + off);
            }
#pragma unroll
            for (int fm = 0; fm < 4; fm++)
#pragma unroll
                for (int fn = 0; fn < 4; fn++) {
                    const uint32_t* bh2 = &bhp[fn >> 1][(fn & 1) * 2];
                    const uint32_t* bl2 = &blp[fn >> 1][(fn & 1) * 2];
                    mma_bf16(acc[fm][fn], ah[fm], bl2);
                    mma_bf16(acc[fm][fn], al[fm], bh2);
                    mma_bf16(acc[fm][fn], ah[fm], bh2);
                }
        }

        if (ci + 1 < NCHUNK) sts_chunk(dsm + ((ci + 1) & 1) * G_STG);
        __syncthreads();
    }

    // ---- epilogue ----
#pragma unroll
    for (int fm = 0; fm < 4; fm++) {
#pragma unroll
        for (int fn = 0; fn < 4; fn++) {
            int ng = n0 + wn + fn * 8 + tq * 2;
#pragma unroll
            for (int half = 0; half < 2; half++) {
                int m = m0 + wm + fm * 16 + g + half * 8;
                float v0 = acc[fm][fn][half * 2 + 0] + bias[ng];
                float v1 = acc[fm][fn][half * 2 + 1] + bias[ng + 1];
                if (MODE == 0) {
                    const int which = ng >> 10;
                    const int h = (ng & (NC - 1)) >> 6;
                    const int d = ng & (HD - 1);
                    float h0, l0, h1, l1;
                    split2(v0, h0, l0); split2(v1, h1, l1);
                    size_t idx = (((size_t)(m >> 11) * NHH + h) * NT + (m & (NT - 1))) * HP + (d >> 1);
                    uint32_t* dh = (which == 0) ? g_qh : (which == 1) ? g_kh : g_vh;
                    uint32_t* dl = (which == 0) ? g_ql : (which == 1) ? g_kl : g_vl;
                    dh[idx] = pack_bf16(h0, h1);
                    dl[idx] = pack_bf16(l0, l1);
                } else {
                    *(float2*)(out + (size_t)m * NGLOB + ng) = make_float2(v0, v1);
                }
            }
        }
    }
}

// ===================== flash attention (pipelined + LDSM) =====================
static constexpr int FP = 36;
// stage layout (bytes): Ksh 0 | Ksl 9216 | Vth 18432 | Vtl 27648
static constexpr int F_STG = 9216;                    // u32 per stage
static constexpr int F_SMEM_BYTES = 2 * F_STG * 4;    // 73728

__global__ __launch_bounds__(256) void flash_mma_kernel()
{
    extern __shared__ uint32_t fsm[];

    const int tid  = threadIdx.x;
    const int warp = tid >> 5, lane = tid & 31;
    const int g = lane >> 2, tq = lane & 3;
    const int qi = blockIdx.x, bh = blockIdx.y;
    const int q0 = qi * 128;
    const int rw = q0 + warp * 16 + g;
    const uint32_t fsm_b = smem_u32(fsm);

    const size_t base = (size_t)bh * NT * HP;
    const uint32_t* __restrict__ qh = g_qh + base;
    const uint32_t* __restrict__ ql = g_ql + base;
    const uint32_t* __restrict__ kh = g_kh + base;
    const uint32_t* __restrict__ kl = g_kl + base;
    const uint32_t* __restrict__ vh = g_vh + base;
    const uint32_t* __restrict__ vl = g_vl + base;

    const int skey = tid >> 5;
    const int spr  = tid & 31;

    // ldmatrix B-side lane mapping
    const int brow_f = (lane >> 4) * 8 + (lane & 7);
    const int bkp    = ((lane >> 3) & 1) * 4;

    uint32_t krh[8], krl[8], vrh[8], vrl[8];

    auto ldg_tile = [&](int kt) {
        const uint32_t* kph = kh + (size_t)kt * 64 * HP;
        const uint32_t* kpl = kl + (size_t)kt * 64 * HP;
        const uint32_t* vph = vh + (size_t)kt * 64 * HP;
        const uint32_t* vpl = vl + (size_t)kt * 64 * HP;
#pragma unroll
        for (int it = 0; it < 8; it++) {
            int key = skey + it * 8;
            krh[it] = kph[key * HP + spr];
            krl[it] = kpl[key * HP + spr];
            vrh[it] = vph[key * HP + spr];
            vrl[it] = vpl[key * HP + spr];
        }
    };
    auto sts_tile = [&](uint32_t* st) {
        uint32_t* Ksh = st;
        uint32_t* Ksl = st + 2304;
        uint16_t* Vth = (uint16_t*)(st + 4608);
        uint16_t* Vtl = (uint16_t*)(st + 6912);
#pragma unroll
        for (int it = 0; it < 8; it++) {
            int key = skey + it * 8;
            Ksh[key * FP + spr] = krh[it];
            Ksl[key * FP + spr] = krl[it];
            int j = spr;
            Vth[(2 * j) * (2 * FP) + key]     = (uint16_t)(vrh[it] & 0xffff);
            Vth[(2 * j + 1) * (2 * FP) + key] = (uint16_t)(vrh[it] >> 16);
            Vtl[(2 * j) * (2 * FP) + key]     = (uint16_t)(vrl[it] & 0xffff);
            Vtl[(2 * j + 1) * (2 * FP) + key] = (uint16_t)(vrl[it] >> 16);
        }
    };

    // Q fragments (rows rw, rw+8; full HD)
    uint32_t qah[4][4], qal[4][4];
#pragma unroll
    for (int s = 0; s < 4; s++) {
        int o0 = rw * HP + s * 8 + tq;
        int o1 = (rw + 8) * HP + s * 8 + tq;
        qah[s][0] = qh[o0]; qah[s][1] = qh[o1];
        qah[s][2] = qh[o0 + 4]; qah[s][3] = qh[o1 + 4];
        qal[s][0] = ql[o0]; qal[s][1] = ql[o1];
        qal[s][2] = ql[o0 + 4]; qal[s][3] = ql[o1 + 4];
    }

    float m_i[2] = {-1e30f, -1e30f}, l_i[2] = {0.f, 0.f};
    float o[8][4] = {};

    const int nkt = 2 * qi + 2;
    ldg_tile(0);
    sts_tile(fsm);
    __syncthreads();

    for (int kt = 0; kt < nkt; kt++) {
        if (kt + 1 < nkt) ldg_tile(kt + 1);

        if (q0 + warp * 16 + 15 >= kt * 64) {
            const uint32_t stb = fsm_b + (kt & 1) * (F_STG * 4);

            // ---- S = Q K^T via ldmatrix (nt pairs) ----
            float s[8][4];
#pragma unroll
            for (int ntp = 0; ntp < 4; ntp++) {
                float sa[8] = {};
#pragma unroll
                for (int ks = 0; ks < 4; ks++) {
                    uint32_t off = ((ntp * 16 + brow_f) * FP + ks * 8 + bkp) * 4;
                    uint32_t kb[4], kbl[4];
                    ldsm_x4(kb,  stb + off);
                    ldsm_x4(kbl, stb + 9216 + off);
                    mma_bf16(sa,     qah[ks], kbl);
                    mma_bf16(sa,     qal[ks], kb);
                    mma_bf16(sa,     qah[ks], kb);
                    mma_bf16(sa + 4, qah[ks], kbl + 2);
                    mma_bf16(sa + 4, qal[ks], kb + 2);
                    mma_bf16(sa + 4, qah[ks], kb + 2);
                }
#pragma unroll
                for (int e = 0; e < 4; e++) {
                    s[2 * ntp][e]     = sa[e];
                    s[2 * ntp + 1][e] = sa[4 + e];
                }
            }

            const bool need_mask = (kt >= 2 * qi);
#pragma unroll
            for (int nt = 0; nt < 8; nt++) {
                int c0 = kt * 64 + nt * 8 + 2 * tq;
#pragma unroll
                for (int r = 0; r < 4; r++) {
                    int col = c0 + (r & 1);
                    int row = rw + (r >> 1) * 8;
                    float v = s[nt][r] * 0.125f;
                    if (need_mask && col > row) v = -1e30f;
                    s[nt][r] = v;
                }
            }

            float sc[2];
#pragma unroll
            for (int r = 0; r < 2; r++) {
                float mx = -1e30f;
#pragma unroll
                for (int nt = 0; nt < 8; nt++)
                    mx = fmaxf(mx, fmaxf(s[nt][2 * r], s[nt][2 * r + 1]));
                mx = fmaxf(mx, __shfl_xor_sync(0xffffffffu, mx, 1));
                mx = fmaxf(mx, __shfl_xor_sync(0xffffffffu, mx, 2));
                float m_new = fmaxf(m_i[r], mx);
                float sum = 0.f;
#pragma unroll
                for (int nt = 0; nt < 8; nt++) {
                    float p0 = __expf(s[nt][2 * r] - m_new);
                    float p1 = __expf(s[nt][2 * r + 1] - m_new);
                    s[nt][2 * r] = p0; s[nt][2 * r + 1] = p1;
                    sum += p0 + p1;
                }
                sum += __shfl_xor_sync(0xffffffffu, sum, 1);
                sum += __shfl_xor_sync(0xffffffffu, sum, 2);
                sc[r]  = __expf(m_i[r] - m_new);
                l_i[r] = l_i[r] * sc[r] + sum;
                m_i[r] = m_new;
            }
#pragma unroll
            for (int nt = 0; nt < 8; nt++) {
                o[nt][0] *= sc[0]; o[nt][1] *= sc[0];
                o[nt][2] *= sc[1]; o[nt][3] *= sc[1];
            }

            // ---- PV via ldmatrix ----
#pragma unroll
            for (int ks = 0; ks < 4; ks++) {
                float ph[8], pl[8];
#pragma unroll
                for (int e = 0; e < 4; e++) {
                    split2(s[2 * ks][e], ph[e], pl[e]);
                    split2(s[2 * ks + 1][e], ph[4 + e], pl[4 + e]);
                }
                uint32_t pah[4] = { pack_bf16(ph[0], ph[1]), pack_bf16(ph[2], ph[3]),
                                    pack_bf16(ph[4], ph[5]), pack_bf16(ph[6], ph[7]) };
                uint32_t pal[4] = { pack_bf16(pl[0], pl[1]), pack_bf16(pl[2], pl[3]),
                                    pack_bf16(pl[4], pl[5]), pack_bf16(pl[6], pl[7]) };
#pragma unroll
                for (int ntp = 0; ntp < 4; ntp++) {
                    uint32_t off = ((ntp * 16 + brow_f) * FP + ks * 8 + bkp) * 4;
                    uint32_t vb[4], vbl[4];
                    ldsm_x4(vb,  stb + 18432 + off);
                    ldsm_x4(vbl, stb + 27648 + off);
                    mma_bf16(o[2 * ntp],     pah, vbl);
                    mma_bf16(o[2 * ntp],     pal, vb);
                    mma_bf16(o[2 * ntp],     pah, vb);
                    mma_bf16(o[2 * ntp + 1], pah, vbl + 2);
                    mma_bf16(o[2 * ntp + 1], pal, vb + 2);
                    mma_bf16(o[2 * ntp + 1], pah, vb + 2);
                }
            }
        }

        if (kt + 1 < nkt) sts_tile(fsm + ((kt + 1) & 1) * F_STG);
        __syncthreads();
    }

    // ---- epilogue ----
    const int b = bh >> 4, h = bh & 15;
    float inv0 = 1.f / l_i[0], inv1 = 1.f / l_i[1];
#pragma unroll
    for (int nt = 0; nt < 8; nt++) {
        int d = h * HD + nt * 8 + 2 * tq;
        *(float2*)(g_y + (size_t)(b * NT + rw) * NC + d) =
            make_float2(o[nt][0] * inv0, o[nt][1] * inv0);
        *(float2*)(g_y + (size_t)(b * NT + rw + 8) * NC + d) =
            make_float2(o[nt][2] * inv1, o[nt][3] * inv1);
    }
}

// ===========================================================================
extern "C" void kernel_launch(void* const* d_in, const int* in_sizes, int n_in,
                              void* d_out, int out_size)
{
    const float* x      = (const float*)d_in[0];
    const float* w_attn = (const float*)d_in[1];
    const float* b_attn = (const float*)d_in[2];
    const float* w_proj = (const float*)d_in[3];
    const float* b_proj = (const float*)d_in[4];
    float* out = (float*)d_out;

    cudaFuncSetAttribute(gemm_bf16_kernel<0, 3 * NC>,
                         cudaFuncAttributeMaxDynamicSharedMemorySize, G_SMEM_BYTES);
    cudaFuncSetAttribute(gemm_bf16_kernel<1, NC>,
                         cudaFuncAttributeMaxDynamicSharedMemorySize, G_SMEM_BYTES);
    cudaFuncSetAttribute(flash_mma_kernel,
                         cudaFuncAttributeMaxDynamicSharedMemorySize, F_SMEM_BYTES);

    dim3 g1(3 * NC / BN, (NB * NT) / BM);   // (24, 64)
    gemm_bf16_kernel<0, 3 * NC><<<g1, 256, G_SMEM_BYTES>>>(x, w_attn, b_attn, nullptr);

    dim3 g2(NT / 128, NB * NHH);            // (16, 64)
    flash_mma_kernel<<<g2, 256, F_SMEM_BYTES>>>();

    dim3 g3(NC / BN, (NB * NT) / BM);       // (8, 64)
    gemm_bf16_kernel<1, NC><<<g3, 256, G_SMEM_BYTES>>>(nullptr, w_proj, b_proj, out);
}

// round 9
// speedup vs baseline: 1.5475x; 1.5475x over previous
#include <cuda_runtime.h>
#include <cuda_bf16.h>
#include <cstdint>
#include <math.h>

#define NB  4
#define NT  2048
#define NC  1024
#define NHH 16
#define HD  64
#define HP  32   // HD/2 packed u32 per row

// ---------------- device-global scratch (no cudaMalloc allowed) ----------------
__device__ uint32_t g_qh[(size_t)NB * NHH * NT * HP];
__device__ uint32_t g_ql[(size_t)NB * NHH * NT * HP];
__device__ uint32_t g_kh[(size_t)NB * NHH * NT * HP];
__device__ uint32_t g_kl[(size_t)NB * NHH * NT * HP];
__device__ uint32_t g_vh[(size_t)NB * NHH * NT * HP];
__device__ uint32_t g_vl[(size_t)NB * NHH * NT * HP];
// pre-split inputs (packed bf16-pair u32, k-pair minor)
__device__ uint32_t g_xh [(size_t)NB * NT * (NC / 2)];        // x   [8192][512]
__device__ uint32_t g_xl [(size_t)NB * NT * (NC / 2)];
__device__ uint32_t g_wah[(size_t)3 * NC * (NC / 2)];         // w_attn^T [3072][512]
__device__ uint32_t g_wal[(size_t)3 * NC * (NC / 2)];
__device__ uint32_t g_wph[(size_t)NC * (NC / 2)];             // w_proj^T [1024][512]
__device__ uint32_t g_wpl[(size_t)NC * (NC / 2)];
__device__ uint32_t g_yh [(size_t)NB * NT * (NC / 2)];        // attn out split [8192][512]
__device__ uint32_t g_yl [(size_t)NB * NT * (NC / 2)];

// ============================ helpers ============================
__device__ __forceinline__ uint32_t pack_bf16(float a, float b) {
    __nv_bfloat162 t = __floats2bfloat162_rn(a, b);
    return *(uint32_t*)&t;
}
__device__ __forceinline__ void split2(float x, float& hi, float& lo) {
    __nv_bfloat16 h = __float2bfloat16(x);
    hi = __bfloat162float(h);
    lo = x - hi;
}
__device__ __forceinline__ void mma_bf16(float* d, const uint32_t* a, const uint32_t* b) {
    asm volatile(
        "mma.sync.aligned.m16n8k16.row.col.f32.bf16.bf16.f32 "
        "{%0,%1,%2,%3}, {%4,%5,%6,%7}, {%8,%9}, {%0,%1,%2,%3};"
        : "+f"(d[0]), "+f"(d[1]), "+f"(d[2]), "+f"(d[3])
        : "r"(a[0]), "r"(a[1]), "r"(a[2]), "r"(a[3]), "r"(b[0]), "r"(b[1]));
}
__device__ __forceinline__ uint32_t smem_u32(const void* p) {
    uint32_t a;
    asm("{ .reg .u64 t; cvta.to.shared.u64 t, %1; cvt.u32.u64 %0, t; }"
        : "=r"(a) : "l"(p));
    return a;
}
__device__ __forceinline__ void cp16(uint32_t dst, const void* src) {
    asm volatile("cp.async.cg.shared.global [%0], [%1], 16;" :: "r"(dst), "l"(src));
}
#define CP_COMMIT() asm volatile("cp.async.commit_group;" ::: "memory")
#define CP_WAIT1()  asm volatile("cp.async.wait_group 1;" ::: "memory")

// ===================== pre-split kernels =====================
__global__ __launch_bounds__(256) void split_pairs_kernel(
    const float* __restrict__ src, uint32_t* __restrict__ dh,
    uint32_t* __restrict__ dl, int npairs)
{
    int i = blockIdx.x * 256 + threadIdx.x;
    if (i < npairs) {
        float2 v = ((const float2*)src)[i];
        float h0, l0, h1, l1;
        split2(v.x, h0, l0); split2(v.y, h1, l1);
        dh[i] = pack_bf16(h0, h1);
        dl[i] = pack_bf16(l0, l1);
    }
}

// transpose+split: w [1024][N] fp32 -> wt_h/wt_l [N][512] packed u32
template <int N>
__global__ __launch_bounds__(256) void split_wT_kernel(
    const float* __restrict__ w, uint32_t* __restrict__ wth, uint32_t* __restrict__ wtl)
{
    __shared__ float ws[32][65];
    const int tid = threadIdx.x;
    const int n0 = blockIdx.x * 64, k0 = blockIdx.y * 32;
#pragma unroll
    for (int it = 0; it < 8; it++) {
        int s = tid + it * 256;
        int r = s >> 6, c = s & 63;
        ws[r][c] = w[(size_t)(k0 + r) * N + n0 + c];
    }
    __syncthreads();
#pragma unroll
    for (int it = 0; it < 4; it++) {
        int s = tid + it * 256;
        int n = s >> 4, kp = s & 15;
        float f0 = ws[2 * kp][n], f1 = ws[2 * kp + 1][n];
        float h0, l0, h1, l1;
        split2(f0, h0, l0); split2(f1, h1, l1);
        size_t o = (size_t)(n0 + n) * (NC / 2) + (k0 >> 1) + kp;
        wth[o] = pack_bf16(h0, h1);
        wtl[o] = pack_bf16(l0, l1);
    }
}

// ===================== bf16x3 GEMM: cp.async 3-stage, pre-split inputs =====================
static constexpr int BM = 128, BN = 128, BK = 32;
static constexpr int KTOT = 1024, NCHUNK = KTOT / BK, KP = KTOT / 2;
static constexpr int LDP = 20;
// stage layout (u32): As_hi 0 | As_lo 2560 | Bs_hi 5120 | Bs_lo 7680
static constexpr int G_STG = 10240;
static constexpr int G_SMEM_BYTES = 3 * G_STG * 4;    // 122880

// MODE 0: A = g_x*, B = g_wa*, epilogue -> split q/k/v + bias
// MODE 1: A = g_y*, B = g_wp*, epilogue -> out fp32 + bias
template <int MODE>
__global__ __launch_bounds__(256) void gemm_bf16_kernel(
    const float* __restrict__ bias, float* __restrict__ out)
{
    extern __shared__ uint32_t dsm[];
    const uint32_t dsm_b = smem_u32(dsm);

    const int tid  = threadIdx.x;
    const int warp = tid >> 5, lane = tid & 31;
    const int g = lane >> 2, tq = lane & 3;
    const int wm = (warp >> 2) * 64;
    const int wn = (warp & 3) * 32;
    const int m0 = blockIdx.y * BM, n0 = blockIdx.x * BN;

    const uint32_t* __restrict__ Ah = (MODE == 0) ? g_xh : g_yh;
    const uint32_t* __restrict__ Al = (MODE == 0) ? g_xl : g_yl;
    const uint32_t* __restrict__ Bh = (MODE == 0) ? g_wah : g_wph;
    const uint32_t* __restrict__ Bl = (MODE == 0) ? g_wal : g_wpl;

    // staging map: s = tid + it*256 -> (row = s>>2, q = s&3), 16B each
    const int srow = tid >> 2, sq = (tid & 3) * 4;

    auto issue = [&](int ci) {
        const int kp0 = ci * (BK / 2);
        const uint32_t st = dsm_b + (ci % 3) * (G_STG * 4);
#pragma unroll
        for (int it = 0; it < 2; it++) {
            int row = srow + it * 64;
            uint32_t doff = (row * LDP + sq) * 4;
            const size_t asrc = (size_t)(m0 + row) * KP + kp0 + sq;
            cp16(st + doff,           Ah + asrc);
            cp16(st + 10240 + doff,   Al + asrc);
            const size_t bsrc = (size_t)(n0 + row) * KP + kp0 + sq;
            cp16(st + 20480 + doff,   Bh + bsrc);
            cp16(st + 30720 + doff,   Bl + bsrc);
        }
    };

    float acc[4][4][4] = {};

    issue(0); CP_COMMIT();
    issue(1); CP_COMMIT();

    for (int ci = 0; ci < NCHUNK; ci++) {
        CP_WAIT1();
        __syncthreads();

        const uint32_t* st = dsm + (ci % 3) * G_STG;
        const uint32_t* As_hi = st;
        const uint32_t* As_lo = st + 2560;
        const uint32_t* Bs_hi = st + 5120;
        const uint32_t* Bs_lo = st + 7680;
#pragma unroll
        for (int ks = 0; ks < 2; ks++) {
            const int pb2 = ks * 8 + tq;
            uint32_t ah[4][4], al[4][4];
#pragma unroll
            for (int fm = 0; fm < 4; fm++) {
                int r0 = (wm + fm * 16 + g) * LDP + pb2;
                int r1 = r0 + 8 * LDP;
                ah[fm][0] = As_hi[r0];     ah[fm][1] = As_hi[r1];
                ah[fm][2] = As_hi[r0 + 4]; ah[fm][3] = As_hi[r1 + 4];
                al[fm][0] = As_lo[r0];     al[fm][1] = As_lo[r1];
                al[fm][2] = As_lo[r0 + 4]; al[fm][3] = As_lo[r1 + 4];
            }
            uint32_t bh[4][2], bl[4][2];
#pragma unroll
            for (int fn = 0; fn < 4; fn++) {
                int o = (wn + fn * 8 + g) * LDP + pb2;
                bh[fn][0] = Bs_hi[o]; bh[fn][1] = Bs_hi[o + 4];
                bl[fn][0] = Bs_lo[o]; bl[fn][1] = Bs_lo[o + 4];
            }
#pragma unroll
            for (int fm = 0; fm < 4; fm++)
#pragma unroll
                for (int fn = 0; fn < 4; fn++) {
                    mma_bf16(acc[fm][fn], ah[fm], bl[fn]);
                    mma_bf16(acc[fm][fn], al[fm], bh[fn]);
                    mma_bf16(acc[fm][fn], ah[fm], bh[fn]);
                }
        }

        if (ci + 2 < NCHUNK) issue(ci + 2);
        CP_COMMIT();
    }

    // ---- epilogue ----
#pragma unroll
    for (int fm = 0; fm < 4; fm++) {
#pragma unroll
        for (int fn = 0; fn < 4; fn++) {
            int ng = n0 + wn + fn * 8 + tq * 2;
#pragma unroll
            for (int half = 0; half < 2; half++) {
                int m = m0 + wm + fm * 16 + g + half * 8;
                float v0 = acc[fm][fn][half * 2 + 0] + bias[ng];
                float v1 = acc[fm][fn][half * 2 + 1] + bias[ng + 1];
                if (MODE == 0) {
                    const int which = ng >> 10;
                    const int h = (ng & (NC - 1)) >> 6;
                    const int d = ng & (HD - 1);
                    float h0, l0, h1, l1;
                    split2(v0, h0, l0); split2(v1, h1, l1);
                    size_t idx = (((size_t)(m >> 11) * NHH + h) * NT + (m & (NT - 1))) * HP + (d >> 1);
                    uint32_t* dh = (which == 0) ? g_qh : (which == 1) ? g_kh : g_vh;
                    uint32_t* dl = (which == 0) ? g_ql : (which == 1) ? g_kl : g_vl;
                    dh[idx] = pack_bf16(h0, h1);
                    dl[idx] = pack_bf16(l0, l1);
                } else {
                    *(float2*)(out + (size_t)m * NC + ng) = make_float2(v0, v1);
                }
            }
        }
    }
}

// ===================== flash attention (R7 structure; split epilogue) =====================
static constexpr int FP = 36;
static constexpr int F_STG = 9216;
static constexpr int F_SMEM_BYTES = 2 * F_STG * 4;    // 73728

__global__ __launch_bounds__(256) void flash_mma_kernel()
{
    extern __shared__ uint32_t fsm[];

    const int tid  = threadIdx.x;
    const int warp = tid >> 5, lane = tid & 31;
    const int g = lane >> 2, tq = lane & 3;
    const int qi = blockIdx.x, bh = blockIdx.y;
    const int q0 = qi * 128;
    const int rw = q0 + warp * 16 + g;

    const size_t base = (size_t)bh * NT * HP;
    const uint32_t* __restrict__ qh = g_qh + base;
    const uint32_t* __restrict__ ql = g_ql + base;
    const uint32_t* __restrict__ kh = g_kh + base;
    const uint32_t* __restrict__ kl = g_kl + base;
    const uint32_t* __restrict__ vh = g_vh + base;
    const uint32_t* __restrict__ vl = g_vl + base;

    const int skey = tid >> 5;
    const int spr  = tid & 31;

    uint32_t krh[8], krl[8], vrh[8], vrl[8];

    auto ldg_tile = [&](int kt) {
        const uint32_t* kph = kh + (size_t)kt * 64 * HP;
        const uint32_t* kpl = kl + (size_t)kt * 64 * HP;
        const uint32_t* vph = vh + (size_t)kt * 64 * HP;
        const uint32_t* vpl = vl + (size_t)kt * 64 * HP;
#pragma unroll
        for (int it = 0; it < 8; it++) {
            int key = skey + it * 8;
            krh[it] = kph[key * HP + spr];
            krl[it] = kpl[key * HP + spr];
            vrh[it] = vph[key * HP + spr];
            vrl[it] = vpl[key * HP + spr];
        }
    };
    auto sts_tile = [&](uint32_t* st) {
        uint32_t* Ksh = st;
        uint32_t* Ksl = st + 2304;
        uint16_t* Vth = (uint16_t*)(st + 4608);
        uint16_t* Vtl = (uint16_t*)(st + 6912);
#pragma unroll
        for (int it = 0; it < 8; it++) {
            int key = skey + it * 8;
            Ksh[key * FP + spr] = krh[it];
            Ksl[key * FP + spr] = krl[it];
            int j = spr;
            Vth[(2 * j) * (2 * FP) + key]     = (uint16_t)(vrh[it] & 0xffff);
            Vth[(2 * j + 1) * (2 * FP) + key] = (uint16_t)(vrh[it] >> 16);
            Vtl[(2 * j) * (2 * FP) + key]     = (uint16_t)(vrl[it] & 0xffff);
            Vtl[(2 * j + 1) * (2 * FP) + key] = (uint16_t)(vrl[it] >> 16);
        }
    };

    uint32_t qah[4][4], qal[4][4];
#pragma unroll
    for (int s = 0; s < 4; s++) {
        int o0 = rw * HP + s * 8 + tq;
        int o1 = (rw + 8) * HP + s * 8 + tq;
        qah[s][0] = qh[o0]; qah[s][1] = qh[o1];
        qah[s][2] = qh[o0 + 4]; qah[s][3] = qh[o1 + 4];
        qal[s][0] = ql[o0]; qal[s][1] = ql[o1];
        qal[s][2] = ql[o0 + 4]; qal[s][3] = ql[o1 + 4];
    }

    float m_i[2] = {-1e30f, -1e30f}, l_i[2] = {0.f, 0.f};
    float o[8][4] = {};

    const int nkt = 2 * qi + 2;
    ldg_tile(0);
    sts_tile(fsm);
    __syncthreads();

    for (int kt = 0; kt < nkt; kt++) {
        if (kt + 1 < nkt) ldg_tile(kt + 1);

        if (q0 + warp * 16 + 15 >= kt * 64) {
            uint32_t* st = fsm + (kt & 1) * F_STG;
            const uint32_t* Ksh = st;
            const uint32_t* Ksl = st + 2304;
            const uint32_t* Vth = st + 4608;
            const uint32_t* Vtl = st + 6912;

            float s[8][4];
#pragma unroll
            for (int nt = 0; nt < 8; nt++) {
                float sa[4] = {};
#pragma unroll
                for (int ks = 0; ks < 4; ks++) {
                    int ob = (nt * 8 + g) * FP + ks * 8 + tq;
                    uint32_t bh2[2] = {Ksh[ob], Ksh[ob + 4]};
                    uint32_t bl2[2] = {Ksl[ob], Ksl[ob + 4]};
                    mma_bf16(sa, qah[ks], bl2);
                    mma_bf16(sa, qal[ks], bh2);
                    mma_bf16(sa, qah[ks], bh2);
                }
                s[nt][0] = sa[0]; s[nt][1] = sa[1]; s[nt][2] = sa[2]; s[nt][3] = sa[3];
            }

            const bool need_mask = (kt >= 2 * qi);
#pragma unroll
            for (int nt = 0; nt < 8; nt++) {
                int c0 = kt * 64 + nt * 8 + 2 * tq;
#pragma unroll
                for (int r = 0; r < 4; r++) {
                    int col = c0 + (r & 1);
                    int row = rw + (r >> 1) * 8;
                    float v = s[nt][r] * 0.125f;
                    if (need_mask && col > row) v = -1e30f;
                    s[nt][r] = v;
                }
            }

            float sc[2];
#pragma unroll
            for (int r = 0; r < 2; r++) {
                float mx = -1e30f;
#pragma unroll
                for (int nt = 0; nt < 8; nt++)
                    mx = fmaxf(mx, fmaxf(s[nt][2 * r], s[nt][2 * r + 1]));
                mx = fmaxf(mx, __shfl_xor_sync(0xffffffffu, mx, 1));
                mx = fmaxf(mx, __shfl_xor_sync(0xffffffffu, mx, 2));
                float m_new = fmaxf(m_i[r], mx);
                float sum = 0.f;
#pragma unroll
                for (int nt = 0; nt < 8; nt++) {
                    float p0 = __expf(s[nt][2 * r] - m_new);
                    float p1 = __expf(s[nt][2 * r + 1] - m_new);
                    s[nt][2 * r] = p0; s[nt][2 * r + 1] = p1;
                    sum += p0 + p1;
                }
                sum += __shfl_xor_sync(0xffffffffu, sum, 1);
                sum += __shfl_xor_sync(0xffffffffu, sum, 2);
                sc[r]  = __expf(m_i[r] - m_new);
                l_i[r] = l_i[r] * sc[r] + sum;
                m_i[r] = m_new;
            }
#pragma unroll
            for (int nt = 0; nt < 8; nt++) {
                o[nt][0] *= sc[0]; o[nt][1] *= sc[0];
                o[nt][2] *= sc[1]; o[nt][3] *= sc[1];
            }

#pragma unroll
            for (int ks = 0; ks < 4; ks++) {
                float ph[8], pl[8];
#pragma unroll
                for (int e = 0; e < 4; e++) {
                    split2(s[2 * ks][e], ph[e], pl[e]);
                    split2(s[2 * ks + 1][e], ph[4 + e], pl[4 + e]);
                }
                uint32_t pah[4] = { pack_bf16(ph[0], ph[1]), pack_bf16(ph[2], ph[3]),
                                    pack_bf16(ph[4], ph[5]), pack_bf16(ph[6], ph[7]) };
                uint32_t pal[4] = { pack_bf16(pl[0], pl[1]), pack_bf16(pl[2], pl[3]),
                                    pack_bf16(pl[4], pl[5]), pack_bf16(pl[6], pl[7]) };
#pragma unroll
                for (int nt = 0; nt < 8; nt++) {
                    int ob = (nt * 8 + g) * FP + ks * 8 + tq;
                    uint32_t bh2[2] = {Vth[ob], Vth[ob + 4]};
                    uint32_t bl2[2] = {Vtl[ob], Vtl[ob + 4]};
                    mma_bf16(o[nt], pah, bl2);
                    mma_bf16(o[nt], pal, bh2);
                    mma_bf16(o[nt], pah, bh2);
                }
            }
        }

        if (kt + 1 < nkt) sts_tile(fsm + ((kt + 1) & 1) * F_STG);
        __syncthreads();
    }

    // ---- epilogue: write PRE-SPLIT y (packed pairs) ----
    const int b = bh >> 4, h = bh & 15;
    float inv0 = 1.f / l_i[0], inv1 = 1.f / l_i[1];
#pragma unroll
    for (int nt = 0; nt < 8; nt++) {
        int dp = h * HP + nt * 4 + tq;   // pair index within row
        float a0 = o[nt][0] * inv0, a1 = o[nt][1] * inv0;
        float b0 = o[nt][2] * inv1, b1 = o[nt][3] * inv1;
        float h0, l0, h1, l1;
        split2(a0, h0, l0); split2(a1, h1, l1);
        g_yh[(size_t)(b * NT + rw) * (NC / 2) + dp] = pack_bf16(h0, h1);
        g_yl[(size_t)(b * NT + rw) * (NC / 2) + dp] = pack_bf16(l0, l1);
        split2(b0, h0, l0); split2(b1, h1, l1);
        g_yh[(size_t)(b * NT + rw + 8) * (NC / 2) + dp] = pack_bf16(h0, h1);
        g_yl[(size_t)(b * NT + rw + 8) * (NC / 2) + dp] = pack_bf16(l0, l1);
    }
}

// ===========================================================================
extern "C" void kernel_launch(void* const* d_in, const int* in_sizes, int n_in,
                              void* d_out, int out_size)
{
    const float* x      = (const float*)d_in[0];
    const float* w_attn = (const float*)d_in[1];
    const float* b_attn = (const float*)d_in[2];
    const float* w_proj = (const float*)d_in[3];
    const float* b_proj = (const float*)d_in[4];
    float* out = (float*)d_out;

    cudaFuncSetAttribute(gemm_bf16_kernel<0>,
                         cudaFuncAttributeMaxDynamicSharedMemorySize, G_SMEM_BYTES);
    cudaFuncSetAttribute(gemm_bf16_kernel<1>,
                         cudaFuncAttributeMaxDynamicSharedMemorySize, G_SMEM_BYTES);
    cudaFuncSetAttribute(flash_mma_kernel,
                         cudaFuncAttributeMaxDynamicSharedMemorySize, F_SMEM_BYTES);

    // pre-split passes
    {
        uint32_t *xh, *xl, *wah, *wal, *wph, *wpl;
        cudaGetSymbolAddress((void**)&xh,  g_xh);
        cudaGetSymbolAddress((void**)&xl,  g_xl);
        cudaGetSymbolAddress((void**)&wah, g_wah);
        cudaGetSymbolAddress((void**)&wal, g_wal);
        cudaGetSymbolAddress((void**)&wph, g_wph);
        cudaGetSymbolAddress((void**)&wpl, g_wpl);
        const int npx = NB * NT * NC / 2;
        split_pairs_kernel<<<(npx + 255) / 256, 256>>>(x, xh, xl, npx);
        split_wT_kernel<3 * NC><<<dim3(3 * NC / 64, NC / 32), 256>>>(w_attn, wah, wal);
        split_wT_kernel<NC><<<dim3(NC / 64, NC / 32), 256>>>(w_proj, wph, wpl);
    }

    dim3 g1(3 * NC / BN, (NB * NT) / BM);   // (24, 64)
    gemm_bf16_kernel<0><<<g1, 256, G_SMEM_BYTES>>>(b_attn, nullptr);

    dim3 g2(NT / 128, NB * NHH);            // (16, 64)
    flash_mma_kernel<<<g2, 256, F_SMEM_BYTES>>>();

    dim3 g3(NC / BN, (NB * NT) / BM);       // (8, 64)
    gemm_bf16_kernel<1><<<g3, 256, G_SMEM_BYTES>>>(b_proj, out);
}

// round 10
// speedup vs baseline: 1.5861x; 1.0250x over previous
#include <cuda_runtime.h>
#include <cuda_bf16.h>
#include <cstdint>
#include <math.h>

#define NB  4
#define NT  2048
#define NC  1024
#define NHH 16
#define HD  64
#define HP  32   // HD/2 packed u32 per row

// ---------------- device-global scratch (no cudaMalloc allowed) ----------------
__device__ uint32_t g_qh[(size_t)NB * NHH * NT * HP];
__device__ uint32_t g_ql[(size_t)NB * NHH * NT * HP];
__device__ uint32_t g_kh[(size_t)NB * NHH * NT * HP];
__device__ uint32_t g_kl[(size_t)NB * NHH * NT * HP];
__device__ uint32_t g_vh[(size_t)NB * NHH * NT * HP];
__device__ uint32_t g_vl[(size_t)NB * NHH * NT * HP];
__device__ uint32_t g_xh [(size_t)NB * NT * (NC / 2)];
__device__ uint32_t g_xl [(size_t)NB * NT * (NC / 2)];
__device__ uint32_t g_wah[(size_t)3 * NC * (NC / 2)];
__device__ uint32_t g_wal[(size_t)3 * NC * (NC / 2)];
__device__ uint32_t g_wph[(size_t)NC * (NC / 2)];
__device__ uint32_t g_wpl[(size_t)NC * (NC / 2)];
__device__ uint32_t g_yh [(size_t)NB * NT * (NC / 2)];
__device__ uint32_t g_yl [(size_t)NB * NT * (NC / 2)];

// ============================ helpers ============================
__device__ __forceinline__ uint32_t pack_bf16(float a, float b) {
    __nv_bfloat162 t = __floats2bfloat162_rn(a, b);
    return *(uint32_t*)&t;
}
__device__ __forceinline__ void split2(float x, float& hi, float& lo) {
    __nv_bfloat16 h = __float2bfloat16(x);
    hi = __bfloat162float(h);
    lo = x - hi;
}
__device__ __forceinline__ void mma_bf16(float* d, const uint32_t* a, const uint32_t* b) {
    asm volatile(
        "mma.sync.aligned.m16n8k16.row.col.f32.bf16.bf16.f32 "
        "{%0,%1,%2,%3}, {%4,%5,%6,%7}, {%8,%9}, {%0,%1,%2,%3};"
        : "+f"(d[0]), "+f"(d[1]), "+f"(d[2]), "+f"(d[3])
        : "r"(a[0]), "r"(a[1]), "r"(a[2]), "r"(a[3]), "r"(b[0]), "r"(b[1]));
}
__device__ __forceinline__ uint32_t smem_u32(const void* p) {
    uint32_t a;
    asm("{ .reg .u64 t; cvta.to.shared.u64 t, %1; cvt.u32.u64 %0, t; }"
        : "=r"(a) : "l"(p));
    return a;
}
__device__ __forceinline__ void cp16(uint32_t dst, const void* src) {
    asm volatile("cp.async.cg.shared.global [%0], [%1], 16;" :: "r"(dst), "l"(src));
}
#define CP_COMMIT() asm volatile("cp.async.commit_group;" ::: "memory")
#define CP_WAIT1()  asm volatile("cp.async.wait_group 1;" ::: "memory")
#define CP_WAIT0()  asm volatile("cp.async.wait_group 0;" ::: "memory")

// ===================== pre-split kernels =====================
__global__ __launch_bounds__(256) void split_pairs_kernel(
    const float* __restrict__ src, uint32_t* __restrict__ dh,
    uint32_t* __restrict__ dl, int npairs)
{
    int i = blockIdx.x * 256 + threadIdx.x;
    if (i < npairs) {
        float2 v = ((const float2*)src)[i];
        float h0, l0, h1, l1;
        split2(v.x, h0, l0); split2(v.y, h1, l1);
        dh[i] = pack_bf16(h0, h1);
        dl[i] = pack_bf16(l0, l1);
    }
}

template <int N>
__global__ __launch_bounds__(256) void split_wT_kernel(
    const float* __restrict__ w, uint32_t* __restrict__ wth, uint32_t* __restrict__ wtl)
{
    __shared__ float ws[32][65];
    const int tid = threadIdx.x;
    const int n0 = blockIdx.x * 64, k0 = blockIdx.y * 32;
#pragma unroll
    for (int it = 0; it < 8; it++) {
        int s = tid + it * 256;
        int r = s >> 6, c = s & 63;
        ws[r][c] = w[(size_t)(k0 + r) * N + n0 + c];
    }
    __syncthreads();
#pragma unroll
    for (int it = 0; it < 4; it++) {
        int s = tid + it * 256;
        int n = s >> 4, kp = s & 15;
        float f0 = ws[2 * kp][n], f1 = ws[2 * kp + 1][n];
        float h0, l0, h1, l1;
        split2(f0, h0, l0); split2(f1, h1, l1);
        size_t o = (size_t)(n0 + n) * (NC / 2) + (k0 >> 1) + kp;
        wth[o] = pack_bf16(h0, h1);
        wtl[o] = pack_bf16(l0, l1);
    }
}

// ===================== bf16x3 GEMM: 2-stage cp.async, occupancy 2 =====================
static constexpr int BM = 128, BN = 128, BK = 32;
static constexpr int KTOT = 1024, NCHUNK = KTOT / BK, KP = KTOT / 2;
static constexpr int LDP = 20;
static constexpr int G_STG = 10240;                   // u32 per stage
static constexpr int G_SMEM_BYTES = 2 * G_STG * 4;    // 81920 -> 2 CTAs/SM

template <int MODE>
__global__ __launch_bounds__(256, 2) void gemm_bf16_kernel(
    const float* __restrict__ bias, float* __restrict__ out)
{
    extern __shared__ uint32_t dsm[];
    const uint32_t dsm_b = smem_u32(dsm);

    const int tid  = threadIdx.x;
    const int warp = tid >> 5, lane = tid & 31;
    const int g = lane >> 2, tq = lane & 3;
    const int wm = (warp >> 2) * 64;
    const int wn = (warp & 3) * 32;
    const int m0 = blockIdx.y * BM, n0 = blockIdx.x * BN;

    const uint32_t* __restrict__ Ah = (MODE == 0) ? g_xh : g_yh;
    const uint32_t* __restrict__ Al = (MODE == 0) ? g_xl : g_yl;
    const uint32_t* __restrict__ Bh = (MODE == 0) ? g_wah : g_wph;
    const uint32_t* __restrict__ Bl = (MODE == 0) ? g_wal : g_wpl;

    const int srow = tid >> 2, sq = (tid & 3) * 4;

    auto issue = [&](int ci) {
        const int kp0 = ci * (BK / 2);
        const uint32_t st = dsm_b + (ci & 1) * (G_STG * 4);
#pragma unroll
        for (int it = 0; it < 2; it++) {
            int row = srow + it * 64;
            uint32_t doff = (row * LDP + sq) * 4;
            const size_t asrc = (size_t)(m0 + row) * KP + kp0 + sq;
            cp16(st + doff,           Ah + asrc);
            cp16(st + 10240 + doff,   Al + asrc);
            const size_t bsrc = (size_t)(n0 + row) * KP + kp0 + sq;
            cp16(st + 20480 + doff,   Bh + bsrc);
            cp16(st + 30720 + doff,   Bl + bsrc);
        }
    };

    float acc[4][4][4] = {};

    issue(0); CP_COMMIT();

    for (int ci = 0; ci < NCHUNK; ci++) {
        if (ci + 1 < NCHUNK) {
            issue(ci + 1); CP_COMMIT();
            CP_WAIT1();
        } else {
            CP_WAIT0();
        }
        __syncthreads();   // stage ci visible to all

        const uint32_t* st = dsm + (ci & 1) * G_STG;
        const uint32_t* As_hi = st;
        const uint32_t* As_lo = st + 2560;
        const uint32_t* Bs_hi = st + 5120;
        const uint32_t* Bs_lo = st + 7680;
#pragma unroll
        for (int ks = 0; ks < 2; ks++) {
            const int pb2 = ks * 8 + tq;
            uint32_t ah[4][4], al[4][4];
#pragma unroll
            for (int fm = 0; fm < 4; fm++) {
                int r0 = (wm + fm * 16 + g) * LDP + pb2;
                int r1 = r0 + 8 * LDP;
                ah[fm][0] = As_hi[r0];     ah[fm][1] = As_hi[r1];
                ah[fm][2] = As_hi[r0 + 4]; ah[fm][3] = As_hi[r1 + 4];
                al[fm][0] = As_lo[r0];     al[fm][1] = As_lo[r1];
                al[fm][2] = As_lo[r0 + 4]; al[fm][3] = As_lo[r1 + 4];
            }
            uint32_t bh[4][2], bl[4][2];
#pragma unroll
            for (int fn = 0; fn < 4; fn++) {
                int o = (wn + fn * 8 + g) * LDP + pb2;
                bh[fn][0] = Bs_hi[o]; bh[fn][1] = Bs_hi[o + 4];
                bl[fn][0] = Bs_lo[o]; bl[fn][1] = Bs_lo[o + 4];
            }
#pragma unroll
            for (int fm = 0; fm < 4; fm++)
#pragma unroll
                for (int fn = 0; fn < 4; fn++) {
                    mma_bf16(acc[fm][fn], ah[fm], bl[fn]);
                    mma_bf16(acc[fm][fn], al[fm], bh[fn]);
                    mma_bf16(acc[fm][fn], ah[fm], bh[fn]);
                }
        }

        __syncthreads();   // all reads of stage ci done before iter ci+1 issues into buf ci&1
    }

    // ---- epilogue ----
#pragma unroll
    for (int fm = 0; fm < 4; fm++) {
#pragma unroll
        for (int fn = 0; fn < 4; fn++) {
            int ng = n0 + wn + fn * 8 + tq * 2;
#pragma unroll
            for (int half = 0; half < 2; half++) {
                int m = m0 + wm + fm * 16 + g + half * 8;
                float v0 = acc[fm][fn][half * 2 + 0] + bias[ng];
                float v1 = acc[fm][fn][half * 2 + 1] + bias[ng + 1];
                if (MODE == 0) {
                    const int which = ng >> 10;
                    const int h = (ng & (NC - 1)) >> 6;
                    const int d = ng & (HD - 1);
                    float h0, l0, h1, l1;
                    split2(v0, h0, l0); split2(v1, h1, l1);
                    size_t idx = (((size_t)(m >> 11) * NHH + h) * NT + (m & (NT - 1))) * HP + (d >> 1);
                    uint32_t* dh = (which == 0) ? g_qh : (which == 1) ? g_kh : g_vh;
                    uint32_t* dl = (which == 0) ? g_ql : (which == 1) ? g_kl : g_vl;
                    dh[idx] = pack_bf16(h0, h1);
                    dl[idx] = pack_bf16(l0, l1);
                } else {
                    *(float2*)(out + (size_t)m * NC + ng) = make_float2(v0, v1);
                }
            }
        }
    }
}

// ===================== flash attention (unchanged from R9) =====================
static constexpr int FP = 36;
static constexpr int F_STG = 9216;
static constexpr int F_SMEM_BYTES = 2 * F_STG * 4;    // 73728

__global__ __launch_bounds__(256) void flash_mma_kernel()
{
    extern __shared__ uint32_t fsm[];

    const int tid  = threadIdx.x;
    const int warp = tid >> 5, lane = tid & 31;
    const int g = lane >> 2, tq = lane & 3;
    const int qi = blockIdx.x, bh = blockIdx.y;
    const int q0 = qi * 128;
    const int rw = q0 + warp * 16 + g;

    const size_t base = (size_t)bh * NT * HP;
    const uint32_t* __restrict__ qh = g_qh + base;
    const uint32_t* __restrict__ ql = g_ql + base;
    const uint32_t* __restrict__ kh = g_kh + base;
    const uint32_t* __restrict__ kl = g_kl + base;
    const uint32_t* __restrict__ vh = g_vh + base;
    const uint32_t* __restrict__ vl = g_vl + base;

    const int skey = tid >> 5;
    const int spr  = tid & 31;

    uint32_t krh[8], krl[8], vrh[8], vrl[8];

    auto ldg_tile = [&](int kt) {
        const uint32_t* kph = kh + (size_t)kt * 64 * HP;
        const uint32_t* kpl = kl + (size_t)kt * 64 * HP;
        const uint32_t* vph = vh + (size_t)kt * 64 * HP;
        const uint32_t* vpl = vl + (size_t)kt * 64 * HP;
#pragma unroll
        for (int it = 0; it < 8; it++) {
            int key = skey + it * 8;
            krh[it] = kph[key * HP + spr];
            krl[it] = kpl[key * HP + spr];
            vrh[it] = vph[key * HP + spr];
            vrl[it] = vpl[key * HP + spr];
        }
    };
    auto sts_tile = [&](uint32_t* st) {
        uint32_t* Ksh = st;
        uint32_t* Ksl = st + 2304;
        uint16_t* Vth = (uint16_t*)(st + 4608);
        uint16_t* Vtl = (uint16_t*)(st + 6912);
#pragma unroll
        for (int it = 0; it < 8; it++) {
            int key = skey + it * 8;
            Ksh[key * FP + spr] = krh[it];
            Ksl[key * FP + spr] = krl[it];
            int j = spr;
            Vth[(2 * j) * (2 * FP) + key]     = (uint16_t)(vrh[it] & 0xffff);
            Vth[(2 * j + 1) * (2 * FP) + key] = (uint16_t)(vrh[it] >> 16);
            Vtl[(2 * j) * (2 * FP) + key]     = (uint16_t)(vrl[it] & 0xffff);
            Vtl[(2 * j + 1) * (2 * FP) + key] = (uint16_t)(vrl[it] >> 16);
        }
    };

    uint32_t qah[4][4], qal[4][4];
#pragma unroll
    for (int s = 0; s < 4; s++) {
        int o0 = rw * HP + s * 8 + tq;
        int o1 = (rw + 8) * HP + s * 8 + tq;
        qah[s][0] = qh[o0]; qah[s][1] = qh[o1];
        qah[s][2] = qh[o0 + 4]; qah[s][3] = qh[o1 + 4];
        qal[s][0] = ql[o0]; qal[s][1] = ql[o1];
        qal[s][2] = ql[o0 + 4]; qal[s][3] = ql[o1 + 4];
    }

    float m_i[2] = {-1e30f, -1e30f}, l_i[2] = {0.f, 0.f};
    float o[8][4] = {};

    const int nkt = 2 * qi + 2;
    ldg_tile(0);
    sts_tile(fsm);
    __syncthreads();

    for (int kt = 0; kt < nkt; kt++) {
        if (kt + 1 < nkt) ldg_tile(kt + 1);

        if (q0 + warp * 16 + 15 >= kt * 64) {
            uint32_t* st = fsm + (kt & 1) * F_STG;
            const uint32_t* Ksh = st;
            const uint32_t* Ksl = st + 2304;
            const uint32_t* Vth = st + 4608;
            const uint32_t* Vtl = st + 6912;

            float s[8][4];
#pragma unroll
            for (int nt = 0; nt < 8; nt++) {
                float sa[4] = {};
#pragma unroll
                for (int ks = 0; ks < 4; ks++) {
                    int ob = (nt * 8 + g) * FP + ks * 8 + tq;
                    uint32_t bh2[2] = {Ksh[ob], Ksh[ob + 4]};
                    uint32_t bl2[2] = {Ksl[ob], Ksl[ob + 4]};
                    mma_bf16(sa, qah[ks], bl2);
                    mma_bf16(sa, qal[ks], bh2);
                    mma_bf16(sa, qah[ks], bh2);
                }
                s[nt][0] = sa[0]; s[nt][1] = sa[1]; s[nt][2] = sa[2]; s[nt][3] = sa[3];
            }

            const bool need_mask = (kt >= 2 * qi);
#pragma unroll
            for (int nt = 0; nt < 8; nt++) {
                int c0 = kt * 64 + nt * 8 + 2 * tq;
#pragma unroll
                for (int r = 0; r < 4; r++) {
                    int col = c0 + (r & 1);
                    int row = rw + (r >> 1) * 8;
                    float v = s[nt][r] * 0.125f;
                    if (need_mask && col > row) v = -1e30f;
                    s[nt][r] = v;
                }
            }

            float sc[2];
#pragma unroll
            for (int r = 0; r < 2; r++) {
                float mx = -1e30f;
#pragma unroll
                for (int nt = 0; nt < 8; nt++)
                    mx = fmaxf(mx, fmaxf(s[nt][2 * r], s[nt][2 * r + 1]));
                mx = fmaxf(mx, __shfl_xor_sync(0xffffffffu, mx, 1));
                mx = fmaxf(mx, __shfl_xor_sync(0xffffffffu, mx, 2));
                float m_new = fmaxf(m_i[r], mx);
                float sum = 0.f;
#pragma unroll
                for (int nt = 0; nt < 8; nt++) {
                    float p0 = __expf(s[nt][2 * r] - m_new);
                    float p1 = __expf(s[nt][2 * r + 1] - m_new);
                    s[nt][2 * r] = p0; s[nt][2 * r + 1] = p1;
                    sum += p0 + p1;
                }
                sum += __shfl_xor_sync(0xffffffffu, sum, 1);
                sum += __shfl_xor_sync(0xffffffffu, sum, 2);
                sc[r]  = __expf(m_i[r] - m_new);
                l_i[r] = l_i[r] * sc[r] + sum;
                m_i[r] = m_new;
            }
#pragma unroll
            for (int nt = 0; nt < 8; nt++) {
                o[nt][0] *= sc[0]; o[nt][1] *= sc[0];
                o[nt][2] *= sc[1]; o[nt][3] *= sc[1];
            }

#pragma unroll
            for (int ks = 0; ks < 4; ks++) {
                float ph[8], pl[8];
#pragma unroll
                for (int e = 0; e < 4; e++) {
                    split2(s[2 * ks][e], ph[e], pl[e]);
                    split2(s[2 * ks + 1][e], ph[4 + e], pl[4 + e]);
                }
                uint32_t pah[4] = { pack_bf16(ph[0], ph[1]), pack_bf16(ph[2], ph[3]),
                                    pack_bf16(ph[4], ph[5]), pack_bf16(ph[6], ph[7]) };
                uint32_t pal[4] = { pack_bf16(pl[0], pl[1]), pack_bf16(pl[2], pl[3]),
                                    pack_bf16(pl[4], pl[5]), pack_bf16(pl[6], pl[7]) };
#pragma unroll
                for (int nt = 0; nt < 8; nt++) {
                    int ob = (nt * 8 + g) * FP + ks * 8 + tq;
                    uint32_t bh2[2] = {Vth[ob], Vth[ob + 4]};
                    uint32_t bl2[2] = {Vtl[ob], Vtl[ob + 4]};
                    mma_bf16(o[nt], pah, bl2);
                    mma_bf16(o[nt], pal, bh2);
                    mma_bf16(o[nt], pah, bh2);
                }
            }
        }

        if (kt + 1 < nkt) sts_tile(fsm + ((kt + 1) & 1) * F_STG);
        __syncthreads();
    }

    // ---- epilogue: write PRE-SPLIT y (packed pairs) ----
    const int b = bh >> 4, h = bh & 15;
    float inv0 = 1.f / l_i[0], inv1 = 1.f / l_i[1];
#pragma unroll
    for (int nt = 0; nt < 8; nt++) {
        int dp = h * HP + nt * 4 + tq;
        float a0 = o[nt][0] * inv0, a1 = o[nt][1] * inv0;
        float b0 = o[nt][2] * inv1, b1 = o[nt][3] * inv1;
        float h0, l0, h1, l1;
        split2(a0, h0, l0); split2(a1, h1, l1);
        g_yh[(size_t)(b * NT + rw) * (NC / 2) + dp] = pack_bf16(h0, h1);
        g_yl[(size_t)(b * NT + rw) * (NC / 2) + dp] = pack_bf16(l0, l1);
        split2(b0, h0, l0); split2(b1, h1, l1);
        g_yh[(size_t)(b * NT + rw + 8) * (NC / 2) + dp] = pack_bf16(h0, h1);
        g_yl[(size_t)(b * NT + rw + 8) * (NC / 2) + dp] = pack_bf16(l0, l1);
    }
}

// ===========================================================================
extern "C" void kernel_launch(void* const* d_in, const int* in_sizes, int n_in,
                              void* d_out, int out_size)
{
    const float* x      = (const float*)d_in[0];
    const float* w_attn = (const float*)d_in[1];
    const float* b_attn = (const float*)d_in[2];
    const float* w_proj = (const float*)d_in[3];
    const float* b_proj = (const float*)d_in[4];
    float* out = (float*)d_out;

    cudaFuncSetAttribute(gemm_bf16_kernel<0>,
                         cudaFuncAttributeMaxDynamicSharedMemorySize, G_SMEM_BYTES);
    cudaFuncSetAttribute(gemm_bf16_kernel<1>,
                         cudaFuncAttributeMaxDynamicSharedMemorySize, G_SMEM_BYTES);
    cudaFuncSetAttribute(flash_mma_kernel,
                         cudaFuncAttributeMaxDynamicSharedMemorySize, F_SMEM_BYTES);

    // pre-split passes
    {
        uint32_t *xh, *xl, *wah, *wal, *wph, *wpl;
        cudaGetSymbolAddress((void**)&xh,  g_xh);
        cudaGetSymbolAddress((void**)&xl,  g_xl);
        cudaGetSymbolAddress((void**)&wah, g_wah);
        cudaGetSymbolAddress((void**)&wal, g_wal);
        cudaGetSymbolAddress((void**)&wph, g_wph);
        cudaGetSymbolAddress((void**)&wpl, g_wpl);
        const int npx = NB * NT * NC / 2;
        split_pairs_kernel<<<(npx + 255) / 256, 256>>>(x, xh, xl, npx);
        split_wT_kernel<3 * NC><<<dim3(3 * NC / 64, NC / 32), 256>>>(w_attn, wah, wal);
        split_wT_kernel<NC><<<dim3(NC / 64, NC / 32), 256>>>(w_proj, wph, wpl);
    }

    dim3 g1(3 * NC / BN, (NB * NT) / BM);   // (24, 64)
    gemm_bf16_kernel<0><<<g1, 256, G_SMEM_BYTES>>>(b_attn, nullptr);

    dim3 g2(NT / 128, NB * NHH);            // (16, 64)
    flash_mma_kernel<<<g2, 256, F_SMEM_BYTES>>>();

    dim3 g3(NC / BN, (NB * NT) / BM);       // (8, 64)
    gemm_bf16_kernel<1><<<g3, 256, G_SMEM_BYTES>>>(b_proj, out);
}

// round 11
// speedup vs baseline: 1.8072x; 1.1394x over previous
#include <cuda_runtime.h>
#include <cuda_bf16.h>
#include <cstdint>
#include <math.h>

#define NB  4
#define NT  2048
#define NC  1024
#define NHH 16
#define HD  64
#define HP  32   // HD/2 packed u32 per row

// ---------------- device-global scratch (no cudaMalloc allowed) ----------------
__device__ uint32_t g_qh[(size_t)NB * NHH * NT * HP];
__device__ uint32_t g_ql[(size_t)NB * NHH * NT * HP];
__device__ uint32_t g_kh[(size_t)NB * NHH * NT * HP];
__device__ uint32_t g_kl[(size_t)NB * NHH * NT * HP];
// V stored TRANSPOSED as bf16 u16: [b,h][d][t]
__device__ uint16_t g_vth[(size_t)NB * NHH * HD * NT];
__device__ uint16_t g_vtl[(size_t)NB * NHH * HD * NT];
__device__ uint32_t g_xh [(size_t)NB * NT * (NC / 2)];
__device__ uint32_t g_xl [(size_t)NB * NT * (NC / 2)];
__device__ uint32_t g_wah[(size_t)3 * NC * (NC / 2)];
__device__ uint32_t g_wal[(size_t)3 * NC * (NC / 2)];
__device__ uint32_t g_wph[(size_t)NC * (NC / 2)];
__device__ uint32_t g_wpl[(size_t)NC * (NC / 2)];
__device__ uint32_t g_yh [(size_t)NB * NT * (NC / 2)];
__device__ uint32_t g_yl [(size_t)NB * NT * (NC / 2)];

// ============================ helpers ============================
__device__ __forceinline__ uint32_t pack_bf16(float a, float b) {
    __nv_bfloat162 t = __floats2bfloat162_rn(a, b);
    return *(uint32_t*)&t;
}
__device__ __forceinline__ void split2(float x, float& hi, float& lo) {
    __nv_bfloat16 h = __float2bfloat16(x);
    hi = __bfloat162float(h);
    lo = x - hi;
}
__device__ __forceinline__ void mma_bf16(float* d, const uint32_t* a, const uint32_t* b) {
    asm volatile(
        "mma.sync.aligned.m16n8k16.row.col.f32.bf16.bf16.f32 "
        "{%0,%1,%2,%3}, {%4,%5,%6,%7}, {%8,%9}, {%0,%1,%2,%3};"
        : "+f"(d[0]), "+f"(d[1]), "+f"(d[2]), "+f"(d[3])
        : "r"(a[0]), "r"(a[1]), "r"(a[2]), "r"(a[3]), "r"(b[0]), "r"(b[1]));
}
__device__ __forceinline__ uint32_t smem_u32(const void* p) {
    uint32_t a;
    asm("{ .reg .u64 t; cvta.to.shared.u64 t, %1; cvt.u32.u64 %0, t; }"
        : "=r"(a) : "l"(p));
    return a;
}
__device__ __forceinline__ void cp16(uint32_t dst, const void* src) {
    asm volatile("cp.async.cg.shared.global [%0], [%1], 16;" :: "r"(dst), "l"(src));
}
#define CP_COMMIT() asm volatile("cp.async.commit_group;" ::: "memory")
#define CP_WAIT1()  asm volatile("cp.async.wait_group 1;" ::: "memory")
#define CP_WAIT0()  asm volatile("cp.async.wait_group 0;" ::: "memory")

// ===================== pre-split kernels =====================
__global__ __launch_bounds__(256) void split_pairs_kernel(
    const float* __restrict__ src, uint32_t* __restrict__ dh,
    uint32_t* __restrict__ dl, int npairs)
{
    int i = blockIdx.x * 256 + threadIdx.x;
    if (i < npairs) {
        float2 v = ((const float2*)src)[i];
        float h0, l0, h1, l1;
        split2(v.x, h0, l0); split2(v.y, h1, l1);
        dh[i] = pack_bf16(h0, h1);
        dl[i] = pack_bf16(l0, l1);
    }
}

template <int N>
__global__ __launch_bounds__(256) void split_wT_kernel(
    const float* __restrict__ w, uint32_t* __restrict__ wth, uint32_t* __restrict__ wtl)
{
    __shared__ float ws[32][65];
    const int tid = threadIdx.x;
    const int n0 = blockIdx.x * 64, k0 = blockIdx.y * 32;
#pragma unroll
    for (int it = 0; it < 8; it++) {
        int s = tid + it * 256;
        int r = s >> 6, c = s & 63;
        ws[r][c] = w[(size_t)(k0 + r) * N + n0 + c];
    }
    __syncthreads();
#pragma unroll
    for (int it = 0; it < 4; it++) {
        int s = tid + it * 256;
        int n = s >> 4, kp = s & 15;
        float f0 = ws[2 * kp][n], f1 = ws[2 * kp + 1][n];
        float h0, l0, h1, l1;
        split2(f0, h0, l0); split2(f1, h1, l1);
        size_t o = (size_t)(n0 + n) * (NC / 2) + (k0 >> 1) + kp;
        wth[o] = pack_bf16(h0, h1);
        wtl[o] = pack_bf16(l0, l1);
    }
}

// ===================== bf16x3 GEMM: 2-stage cp.async, occupancy 2 =====================
static constexpr int BM = 128, BN = 128, BK = 32;
static constexpr int KTOT = 1024, NCHUNK = KTOT / BK, KP = KTOT / 2;
static constexpr int LDP = 20;
static constexpr int G_STG = 10240;                   // u32 per stage
static constexpr int G_SMEM_BYTES = 2 * G_STG * 4;    // 81920 -> 2 CTAs/SM

template <int MODE>
__global__ __launch_bounds__(256, 2) void gemm_bf16_kernel(
    const float* __restrict__ bias, float* __restrict__ out)
{
    extern __shared__ uint32_t dsm[];
    const uint32_t dsm_b = smem_u32(dsm);

    const int tid  = threadIdx.x;
    const int warp = tid >> 5, lane = tid & 31;
    const int g = lane >> 2, tq = lane & 3;
    const int wm = (warp >> 2) * 64;
    const int wn = (warp & 3) * 32;
    const int m0 = blockIdx.y * BM, n0 = blockIdx.x * BN;

    const uint32_t* __restrict__ Ah = (MODE == 0) ? g_xh : g_yh;
    const uint32_t* __restrict__ Al = (MODE == 0) ? g_xl : g_yl;
    const uint32_t* __restrict__ Bh = (MODE == 0) ? g_wah : g_wph;
    const uint32_t* __restrict__ Bl = (MODE == 0) ? g_wal : g_wpl;

    const int srow = tid >> 2, sq = (tid & 3) * 4;

    auto issue = [&](int ci) {
        const int kp0 = ci * (BK / 2);
        const uint32_t st = dsm_b + (ci & 1) * (G_STG * 4);
#pragma unroll
        for (int it = 0; it < 2; it++) {
            int row = srow + it * 64;
            uint32_t doff = (row * LDP + sq) * 4;
            const size_t asrc = (size_t)(m0 + row) * KP + kp0 + sq;
            cp16(st + doff,           Ah + asrc);
            cp16(st + 10240 + doff,   Al + asrc);
            const size_t bsrc = (size_t)(n0 + row) * KP + kp0 + sq;
            cp16(st + 20480 + doff,   Bh + bsrc);
            cp16(st + 30720 + doff,   Bl + bsrc);
        }
    };

    float acc[4][4][4] = {};

    issue(0); CP_COMMIT();

    for (int ci = 0; ci < NCHUNK; ci++) {
        if (ci + 1 < NCHUNK) {
            issue(ci + 1); CP_COMMIT();
            CP_WAIT1();
        } else {
            CP_WAIT0();
        }
        __syncthreads();

        const uint32_t* st = dsm + (ci & 1) * G_STG;
        const uint32_t* As_hi = st;
        const uint32_t* As_lo = st + 2560;
        const uint32_t* Bs_hi = st + 5120;
        const uint32_t* Bs_lo = st + 7680;
#pragma unroll
        for (int ks = 0; ks < 2; ks++) {
            const int pb2 = ks * 8 + tq;
            uint32_t ah[4][4], al[4][4];
#pragma unroll
            for (int fm = 0; fm < 4; fm++) {
                int r0 = (wm + fm * 16 + g) * LDP + pb2;
                int r1 = r0 + 8 * LDP;
                ah[fm][0] = As_hi[r0];     ah[fm][1] = As_hi[r1];
                ah[fm][2] = As_hi[r0 + 4]; ah[fm][3] = As_hi[r1 + 4];
                al[fm][0] = As_lo[r0];     al[fm][1] = As_lo[r1];
                al[fm][2] = As_lo[r0 + 4]; al[fm][3] = As_lo[r1 + 4];
            }
            uint32_t bh[4][2], bl[4][2];
#pragma unroll
            for (int fn = 0; fn < 4; fn++) {
                int o = (wn + fn * 8 + g) * LDP + pb2;
                bh[fn][0] = Bs_hi[o]; bh[fn][1] = Bs_hi[o + 4];
                bl[fn][0] = Bs_lo[o]; bl[fn][1] = Bs_lo[o + 4];
            }
#pragma unroll
            for (int fm = 0; fm < 4; fm++)
#pragma unroll
                for (int fn = 0; fn < 4; fn++) {
                    mma_bf16(acc[fm][fn], ah[fm], bl[fn]);
                    mma_bf16(acc[fm][fn], al[fm], bh[fn]);
                    mma_bf16(acc[fm][fn], ah[fm], bh[fn]);
                }
        }

        __syncthreads();
    }

    // ---- epilogue ----
#pragma unroll
    for (int fm = 0; fm < 4; fm++) {
#pragma unroll
        for (int fn = 0; fn < 4; fn++) {
            int ng = n0 + wn + fn * 8 + tq * 2;
#pragma unroll
            for (int half = 0; half < 2; half++) {
                int m = m0 + wm + fm * 16 + g + half * 8;
                float v0 = acc[fm][fn][half * 2 + 0] + bias[ng];
                float v1 = acc[fm][fn][half * 2 + 1] + bias[ng + 1];
                if (MODE == 0) {
                    const int which = ng >> 10;
                    const int h = (ng & (NC - 1)) >> 6;
                    const int d = ng & (HD - 1);
                    float h0, l0, h1, l1;
                    split2(v0, h0, l0); split2(v1, h1, l1);
                    uint32_t ph = pack_bf16(h0, h1), pl = pack_bf16(l0, l1);
                    const int b = m >> 11, t = m & (NT - 1);
                    if (which == 2) {
                        // V transposed: [b,h][d][t] u16
                        size_t vb = ((size_t)(b * NHH + h) * HD + d) * NT + t;
                        g_vth[vb]      = (uint16_t)(ph & 0xffff);
                        g_vth[vb + NT] = (uint16_t)(ph >> 16);
                        g_vtl[vb]      = (uint16_t)(pl & 0xffff);
                        g_vtl[vb + NT] = (uint16_t)(pl >> 16);
                    } else {
                        size_t idx = (((size_t)b * NHH + h) * NT + t) * HP + (d >> 1);
                        uint32_t* dh = (which == 0) ? g_qh : g_kh;
                        uint32_t* dl = (which == 0) ? g_ql : g_kl;
                        dh[idx] = ph;
                        dl[idx] = pl;
                    }
                } else {
                    *(float2*)(out + (size_t)m * NC + ng) = make_float2(v0, v1);
                }
            }
        }
    }
}

// ===================== flash attention: cp.async staging, occupancy 2 =====================
static constexpr int FP = 36;
// stage layout (u32): Ksh 0 | Ksl 2304 | Vth 4608 | Vtl 6912
static constexpr int F_STG = 9216;
static constexpr int F_SMEM_BYTES = 2 * F_STG * 4;    // 73728 -> 2 CTAs/SM

__global__ __launch_bounds__(256, 2) void flash_mma_kernel()
{
    extern __shared__ uint32_t fsm[];
    const uint32_t fsm_b = smem_u32(fsm);

    const int tid  = threadIdx.x;
    const int warp = tid >> 5, lane = tid & 31;
    const int g = lane >> 2, tq = lane & 3;
    const int qi = blockIdx.x, bh = blockIdx.y;
    const int q0 = qi * 128;
    const int rw = q0 + warp * 16 + g;

    const size_t base = (size_t)bh * NT * HP;
    const uint32_t* __restrict__ qh = g_qh + base;
    const uint32_t* __restrict__ ql = g_ql + base;
    const uint32_t* __restrict__ kh = g_kh + base;
    const uint32_t* __restrict__ kl = g_kl + base;
    const uint32_t* __restrict__ vth32 = (const uint32_t*)(const void*)g_vth
                                         + (size_t)bh * HD * (NT / 2);
    const uint32_t* __restrict__ vtl32 = (const uint32_t*)(const void*)g_vtl
                                         + (size_t)bh * HD * (NT / 2);

    // cp.async staging: chunk c -> row = c>>3 (key for K, d for Vt), pr = (c&7)*4
    auto issue = [&](int kt) {
        const uint32_t st = fsm_b + (kt & 1) * (F_STG * 4);
#pragma unroll
        for (int it = 0; it < 2; it++) {
            int c = tid + it * 256;
            int row = c >> 3, pr = (c & 7) * 4;
            uint32_t doff = (row * FP + pr) * 4;
            const size_t ksrc = (size_t)(kt * 64 + row) * HP + pr;
            cp16(st + doff,         kh + ksrc);
            cp16(st + 9216 + doff,  kl + ksrc);
            const size_t vsrc = (size_t)row * (NT / 2) + (size_t)kt * 32 + pr;
            cp16(st + 18432 + doff, vth32 + vsrc);
            cp16(st + 27648 + doff, vtl32 + vsrc);
        }
    };

    // Q fragments (rows rw, rw+8; full HD)
    uint32_t qah[4][4], qal[4][4];
#pragma unroll
    for (int s = 0; s < 4; s++) {
        int o0 = rw * HP + s * 8 + tq;
        int o1 = (rw + 8) * HP + s * 8 + tq;
        qah[s][0] = qh[o0]; qah[s][1] = qh[o1];
        qah[s][2] = qh[o0 + 4]; qah[s][3] = qh[o1 + 4];
        qal[s][0] = ql[o0]; qal[s][1] = ql[o1];
        qal[s][2] = ql[o0 + 4]; qal[s][3] = ql[o1 + 4];
    }

    float m_i[2] = {-1e30f, -1e30f}, l_i[2] = {0.f, 0.f};
    float o[8][4] = {};

    const int nkt = 2 * qi + 2;
    issue(0); CP_COMMIT();

    for (int kt = 0; kt < nkt; kt++) {
        if (kt + 1 < nkt) {
            issue(kt + 1); CP_COMMIT();
            CP_WAIT1();
        } else {
            CP_WAIT0();
        }
        __syncthreads();

        if (q0 + warp * 16 + 15 >= kt * 64) {
            uint32_t* st = fsm + (kt & 1) * F_STG;
            const uint32_t* Ksh = st;
            const uint32_t* Ksl = st + 2304;
            const uint32_t* Vth = st + 4608;
            const uint32_t* Vtl = st + 6912;

            float s[8][4];
#pragma unroll
            for (int nt = 0; nt < 8; nt++) {
                float sa[4] = {};
#pragma unroll
                for (int ks = 0; ks < 4; ks++) {
                    int ob = (nt * 8 + g) * FP + ks * 8 + tq;
                    uint32_t bh2[2] = {Ksh[ob], Ksh[ob + 4]};
                    uint32_t bl2[2] = {Ksl[ob], Ksl[ob + 4]};
                    mma_bf16(sa, qah[ks], bl2);
                    mma_bf16(sa, qal[ks], bh2);
                    mma_bf16(sa, qah[ks], bh2);
                }
                s[nt][0] = sa[0]; s[nt][1] = sa[1]; s[nt][2] = sa[2]; s[nt][3] = sa[3];
            }

            const bool need_mask = (kt >= 2 * qi);
#pragma unroll
            for (int nt = 0; nt < 8; nt++) {
                int c0 = kt * 64 + nt * 8 + 2 * tq;
#pragma unroll
                for (int r = 0; r < 4; r++) {
                    int col = c0 + (r & 1);
                    int row = rw + (r >> 1) * 8;
                    float v = s[nt][r] * 0.125f;
                    if (need_mask && col > row) v = -1e30f;
                    s[nt][r] = v;
                }
            }

            float sc[2];
#pragma unroll
            for (int r = 0; r < 2; r++) {
                float mx = -1e30f;
#pragma unroll
                for (int nt = 0; nt < 8; nt++)
                    mx = fmaxf(mx, fmaxf(s[nt][2 * r], s[nt][2 * r + 1]));
                mx = fmaxf(mx, __shfl_xor_sync(0xffffffffu, mx, 1));
                mx = fmaxf(mx, __shfl_xor_sync(0xffffffffu, mx, 2));
                float m_new = fmaxf(m_i[r], mx);
                float sum = 0.f;
#pragma unroll
                for (int nt = 0; nt < 8; nt++) {
                    float p0 = __expf(s[nt][2 * r] - m_new);
                    float p1 = __expf(s[nt][2 * r + 1] - m_new);
                    s[nt][2 * r] = p0; s[nt][2 * r + 1] = p1;
                    sum += p0 + p1;
                }
                sum += __shfl_xor_sync(0xffffffffu, sum, 1);
                sum += __shfl_xor_sync(0xffffffffu, sum, 2);
                sc[r]  = __expf(m_i[r] - m_new);
                l_i[r] = l_i[r] * sc[r] + sum;
                m_i[r] = m_new;
            }
#pragma unroll
            for (int nt = 0; nt < 8; nt++) {
                o[nt][0] *= sc[0]; o[nt][1] *= sc[0];
                o[nt][2] *= sc[1]; o[nt][3] *= sc[1];
            }

#pragma unroll
            for (int ks = 0; ks < 4; ks++) {
                float ph[8], pl[8];
#pragma unroll
                for (int e = 0; e < 4; e++) {
                    split2(s[2 * ks][e], ph[e], pl[e]);
                    split2(s[2 * ks + 1][e], ph[4 + e], pl[4 + e]);
                }
                uint32_t pah[4] = { pack_bf16(ph[0], ph[1]), pack_bf16(ph[2], ph[3]),
                                    pack_bf16(ph[4], ph[5]), pack_bf16(ph[6], ph[7]) };
                uint32_t pal[4] = { pack_bf16(pl[0], pl[1]), pack_bf16(pl[2], pl[3]),
                                    pack_bf16(pl[4], pl[5]), pack_bf16(pl[6], pl[7]) };
#pragma unroll
                for (int nt = 0; nt < 8; nt++) {
                    int ob = (nt * 8 + g) * FP + ks * 8 + tq;
                    uint32_t bh2[2] = {Vth[ob], Vth[ob + 4]};
                    uint32_t bl2[2] = {Vtl[ob], Vtl[ob + 4]};
                    mma_bf16(o[nt], pah, bl2);
                    mma_bf16(o[nt], pal, bh2);
                    mma_bf16(o[nt], pah, bh2);
                }
            }
        }

        __syncthreads();
    }

    // ---- epilogue: write PRE-SPLIT y (packed pairs) ----
    const int b = bh >> 4, h = bh & 15;
    float inv0 = 1.f / l_i[0], inv1 = 1.f / l_i[1];
#pragma unroll
    for (int nt = 0; nt < 8; nt++) {
        int dp = h * HP + nt * 4 + tq;
        float a0 = o[nt][0] * inv0, a1 = o[nt][1] * inv0;
        float b0 = o[nt][2] * inv1, b1 = o[nt][3] * inv1;
        float h0, l0, h1, l1;
        split2(a0, h0, l0); split2(a1, h1, l1);
        g_yh[(size_t)(b * NT + rw) * (NC / 2) + dp] = pack_bf16(h0, h1);
        g_yl[(size_t)(b * NT + rw) * (NC / 2) + dp] = pack_bf16(l0, l1);
        split2(b0, h0, l0); split2(b1, h1, l1);
        g_yh[(size_t)(b * NT + rw + 8) * (NC / 2) + dp] = pack_bf16(h0, h1);
        g_yl[(size_t)(b * NT + rw + 8) * (NC / 2) + dp] = pack_bf16(l0, l1);
    }
}

// ===========================================================================
extern "C" void kernel_launch(void* const* d_in, const int* in_sizes, int n_in,
                              void* d_out, int out_size)
{
    const float* x      = (const float*)d_in[0];
    const float* w_attn = (const float*)d_in[1];
    const float* b_attn = (const float*)d_in[2];
    const float* w_proj = (const float*)d_in[3];
    const float* b_proj = (const float*)d_in[4];
    float* out = (float*)d_out;

    cudaFuncSetAttribute(gemm_bf16_kernel<0>,
                         cudaFuncAttributeMaxDynamicSharedMemorySize, G_SMEM_BYTES);
    cudaFuncSetAttribute(gemm_bf16_kernel<1>,
                         cudaFuncAttributeMaxDynamicSharedMemorySize, G_SMEM_BYTES);
    cudaFuncSetAttribute(flash_mma_kernel,
                         cudaFuncAttributeMaxDynamicSharedMemorySize, F_SMEM_BYTES);

    // pre-split passes
    {
        uint32_t *xh, *xl, *wah, *wal, *wph, *wpl;
        cudaGetSymbolAddress((void**)&xh,  g_xh);
        cudaGetSymbolAddress((void**)&xl,  g_xl);
        cudaGetSymbolAddress((void**)&wah, g_wah);
        cudaGetSymbolAddress((void**)&wal, g_wal);
        cudaGetSymbolAddress((void**)&wph, g_wph);
        cudaGetSymbolAddress((void**)&wpl, g_wpl);
        const int npx = NB * NT * NC / 2;
        split_pairs_kernel<<<(npx + 255) / 256, 256>>>(x, xh, xl, npx);
        split_wT_kernel<3 * NC><<<dim3(3 * NC / 64, NC / 32), 256>>>(w_attn, wah, wal);
        split_wT_kernel<NC><<<dim3(NC / 64, NC / 32), 256>>>(w_proj, wph, wpl);
    }

    dim3 g1(3 * NC / BN, (NB * NT) / BM);   // (24, 64)
    gemm_bf16_kernel<0><<<g1, 256, G_SMEM_BYTES>>>(b_attn, nullptr);

    dim3 g2(NT / 128, NB * NHH);            // (16, 64)
    flash_mma_kernel<<<g2, 256, F_SMEM_BYTES>>>();

    dim3 g3(NC / BN, (NB * NT) / BM);       // (8, 64)
    gemm_bf16_kernel<1><<<g3, 256, G_SMEM_BYTES>>>(b_proj, out);
}

// round 12
// speedup vs baseline: 2.2374x; 1.2380x over previous
#include <cuda_runtime.h>
#include <cuda_bf16.h>
#include <cuda_fp16.h>
#include <cstdint>
#include <math.h>

#define NB  4
#define NT  2048
#define NC  1024
#define NHH 16
#define HD  64
#define HP  32   // HD/2 packed u32 per row

// ---------------- device-global scratch (no cudaMalloc allowed) ----------------
// flash inputs: bf16 split (3-pass, accuracy-critical)
__device__ uint32_t g_qh[(size_t)NB * NHH * NT * HP];
__device__ uint32_t g_ql[(size_t)NB * NHH * NT * HP];
__device__ uint32_t g_kh[(size_t)NB * NHH * NT * HP];
__device__ uint32_t g_kl[(size_t)NB * NHH * NT * HP];
__device__ uint16_t g_vth[(size_t)NB * NHH * HD * NT];   // V^T bf16 [b,h][d][t]
__device__ uint16_t g_vtl[(size_t)NB * NHH * HD * NT];
// GEMM inputs: fp16 (A single, B split)
__device__ uint32_t g_x16 [(size_t)NB * NT * (NC / 2)];      // x fp16x2 [8192][512]
__device__ uint32_t g_wa16h[(size_t)3 * NC * (NC / 2)];      // w_attn^T fp16 hi
__device__ uint32_t g_wa16l[(size_t)3 * NC * (NC / 2)];      // w_attn^T fp16 lo
__device__ uint32_t g_wp16h[(size_t)NC * (NC / 2)];          // w_proj^T fp16 hi
__device__ uint32_t g_wp16l[(size_t)NC * (NC / 2)];
__device__ uint32_t g_y16 [(size_t)NB * NT * (NC / 2)];      // attn out fp16x2

// ============================ helpers ============================
__device__ __forceinline__ uint32_t pack_bf16(float a, float b) {
    __nv_bfloat162 t = __floats2bfloat162_rn(a, b);
    return *(uint32_t*)&t;
}
__device__ __forceinline__ uint32_t pack_f16(float a, float b) {
    __half2 t = __floats2half2_rn(a, b);
    return *(uint32_t*)&t;
}
__device__ __forceinline__ void split2(float x, float& hi, float& lo) {
    __nv_bfloat16 h = __float2bfloat16(x);
    hi = __bfloat162float(h);
    lo = x - hi;
}
__device__ __forceinline__ void split2h(float x, float& hi, float& lo) {
    __half h = __float2half_rn(x);
    hi = __half2float(h);
    lo = x - hi;
}
__device__ __forceinline__ void mma_bf16(float* d, const uint32_t* a, const uint32_t* b) {
    asm volatile(
        "mma.sync.aligned.m16n8k16.row.col.f32.bf16.bf16.f32 "
        "{%0,%1,%2,%3}, {%4,%5,%6,%7}, {%8,%9}, {%0,%1,%2,%3};"
        : "+f"(d[0]), "+f"(d[1]), "+f"(d[2]), "+f"(d[3])
        : "r"(a[0]), "r"(a[1]), "r"(a[2]), "r"(a[3]), "r"(b[0]), "r"(b[1]));
}
__device__ __forceinline__ void mma_f16(float* d, const uint32_t* a, const uint32_t* b) {
    asm volatile(
        "mma.sync.aligned.m16n8k16.row.col.f32.f16.f16.f32 "
        "{%0,%1,%2,%3}, {%4,%5,%6,%7}, {%8,%9}, {%0,%1,%2,%3};"
        : "+f"(d[0]), "+f"(d[1]), "+f"(d[2]), "+f"(d[3])
        : "r"(a[0]), "r"(a[1]), "r"(a[2]), "r"(a[3]), "r"(b[0]), "r"(b[1]));
}
__device__ __forceinline__ uint32_t smem_u32(const void* p) {
    uint32_t a;
    asm("{ .reg .u64 t; cvta.to.shared.u64 t, %1; cvt.u32.u64 %0, t; }"
        : "=r"(a) : "l"(p));
    return a;
}
__device__ __forceinline__ void cp16(uint32_t dst, const void* src) {
    asm volatile("cp.async.cg.shared.global [%0], [%1], 16;" :: "r"(dst), "l"(src));
}
#define CP_COMMIT() asm volatile("cp.async.commit_group;" ::: "memory")
#define CP_WAIT1()  asm volatile("cp.async.wait_group 1;" ::: "memory")
#define CP_WAIT0()  asm volatile("cp.async.wait_group 0;" ::: "memory")

// ===================== pre-split kernels =====================
__global__ __launch_bounds__(256) void split_x16_kernel(
    const float* __restrict__ src, uint32_t* __restrict__ d16, int npairs)
{
    int i = blockIdx.x * 256 + threadIdx.x;
    if (i < npairs) {
        float2 v = ((const float2*)src)[i];
        d16[i] = pack_f16(v.x, v.y);
    }
}

// transpose + fp16-split: w [1024][N] fp32 -> [N][512] fp16 hi/lo packed
template <int N>
__global__ __launch_bounds__(256) void split_wT16_kernel(
    const float* __restrict__ w, uint32_t* __restrict__ wth, uint32_t* __restrict__ wtl)
{
    __shared__ float ws[32][65];
    const int tid = threadIdx.x;
    const int n0 = blockIdx.x * 64, k0 = blockIdx.y * 32;
#pragma unroll
    for (int it = 0; it < 8; it++) {
        int s = tid + it * 256;
        int r = s >> 6, c = s & 63;
        ws[r][c] = w[(size_t)(k0 + r) * N + n0 + c];
    }
    __syncthreads();
#pragma unroll
    for (int it = 0; it < 4; it++) {
        int s = tid + it * 256;
        int n = s >> 4, kp = s & 15;
        float f0 = ws[2 * kp][n], f1 = ws[2 * kp + 1][n];
        float h0, l0, h1, l1;
        split2h(f0, h0, l0); split2h(f1, h1, l1);
        size_t o = (size_t)(n0 + n) * (NC / 2) + (k0 >> 1) + kp;
        wth[o] = pack_f16(h0, h1);
        wtl[o] = pack_f16(l0, l1);
    }
}

// ===================== fp16 2-pass GEMM: 2-stage cp.async, occupancy 2 =====================
static constexpr int BM = 128, BN = 128, BK = 32;
static constexpr int KTOT = 1024, NCHUNK = KTOT / BK, KP = KTOT / 2;
static constexpr int LDP = 20;
// stage layout (u32): A 0 | Bh 2560 | Bl 5120 ; stage = 7680 u32
static constexpr int G_STG = 7680;
static constexpr int G_SMEM_BYTES = 2 * G_STG * 4;    // 61440 -> 2 CTAs/SM

template <int MODE>
__global__ __launch_bounds__(256, 2) void gemm_f16_kernel(
    const float* __restrict__ bias, float* __restrict__ out)
{
    extern __shared__ uint32_t dsm[];
    const uint32_t dsm_b = smem_u32(dsm);

    const int tid  = threadIdx.x;
    const int warp = tid >> 5, lane = tid & 31;
    const int g = lane >> 2, tq = lane & 3;
    const int wm = (warp >> 2) * 64;
    const int wn = (warp & 3) * 32;
    const int m0 = blockIdx.y * BM, n0 = blockIdx.x * BN;

    const uint32_t* __restrict__ Ax = (MODE == 0) ? g_x16 : g_y16;
    const uint32_t* __restrict__ Bh = (MODE == 0) ? g_wa16h : g_wp16h;
    const uint32_t* __restrict__ Bl = (MODE == 0) ? g_wa16l : g_wp16l;

    // staging: chunk c -> row = c>>2, sq = (c&3)*4 (16B each); 512 chunks per buffer
    const int srow = tid >> 2, sq = (tid & 3) * 4;

    auto issue = [&](int ci) {
        const int kp0 = ci * (BK / 2);
        const uint32_t st = dsm_b + (ci & 1) * (G_STG * 4);
#pragma unroll
        for (int it = 0; it < 2; it++) {
            int row = srow + it * 64;
            uint32_t doff = (row * LDP + sq) * 4;
            cp16(st + doff, Ax + (size_t)(m0 + row) * KP + kp0 + sq);
            const size_t bsrc = (size_t)(n0 + row) * KP + kp0 + sq;
            cp16(st + 10240 + doff, Bh + bsrc);
            cp16(st + 20480 + doff, Bl + bsrc);
        }
    };

    float acc[4][4][4] = {};

    issue(0); CP_COMMIT();

    for (int ci = 0; ci < NCHUNK; ci++) {
        if (ci + 1 < NCHUNK) {
            issue(ci + 1); CP_COMMIT();
            CP_WAIT1();
        } else {
            CP_WAIT0();
        }
        __syncthreads();

        const uint32_t* st = dsm + (ci & 1) * G_STG;
        const uint32_t* As   = st;
        const uint32_t* Bs_h = st + 2560;
        const uint32_t* Bs_l = st + 5120;
#pragma unroll
        for (int ks = 0; ks < 2; ks++) {
            const int pb2 = ks * 8 + tq;
            uint32_t ah[4][4];
#pragma unroll
            for (int fm = 0; fm < 4; fm++) {
                int r0 = (wm + fm * 16 + g) * LDP + pb2;
                int r1 = r0 + 8 * LDP;
                ah[fm][0] = As[r0];     ah[fm][1] = As[r1];
                ah[fm][2] = As[r0 + 4]; ah[fm][3] = As[r1 + 4];
            }
            uint32_t bh[4][2], bl[4][2];
#pragma unroll
            for (int fn = 0; fn < 4; fn++) {
                int o = (wn + fn * 8 + g) * LDP + pb2;
                bh[fn][0] = Bs_h[o]; bh[fn][1] = Bs_h[o + 4];
                bl[fn][0] = Bs_l[o]; bl[fn][1] = Bs_l[o + 4];
            }
#pragma unroll
            for (int fm = 0; fm < 4; fm++)
#pragma unroll
                for (int fn = 0; fn < 4; fn++) {
                    mma_f16(acc[fm][fn], ah[fm], bl[fn]);
                    mma_f16(acc[fm][fn], ah[fm], bh[fn]);
                }
        }

        __syncthreads();
    }

    // ---- epilogue ----
#pragma unroll
    for (int fm = 0; fm < 4; fm++) {
#pragma unroll
        for (int fn = 0; fn < 4; fn++) {
            int ng = n0 + wn + fn * 8 + tq * 2;
#pragma unroll
            for (int half = 0; half < 2; half++) {
                int m = m0 + wm + fm * 16 + g + half * 8;
                float v0 = acc[fm][fn][half * 2 + 0] + bias[ng];
                float v1 = acc[fm][fn][half * 2 + 1] + bias[ng + 1];
                if (MODE == 0) {
                    const int which = ng >> 10;
                    const int h = (ng & (NC - 1)) >> 6;
                    const int d = ng & (HD - 1);
                    float h0, l0, h1, l1;
                    split2(v0, h0, l0); split2(v1, h1, l1);
                    uint32_t ph = pack_bf16(h0, h1), pl = pack_bf16(l0, l1);
                    const int b = m >> 11, t = m & (NT - 1);
                    if (which == 2) {
                        size_t vb = ((size_t)(b * NHH + h) * HD + d) * NT + t;
                        g_vth[vb]      = (uint16_t)(ph & 0xffff);
                        g_vth[vb + NT] = (uint16_t)(ph >> 16);
                        g_vtl[vb]      = (uint16_t)(pl & 0xffff);
                        g_vtl[vb + NT] = (uint16_t)(pl >> 16);
                    } else {
                        size_t idx = (((size_t)b * NHH + h) * NT + t) * HP + (d >> 1);
                        uint32_t* dh = (which == 0) ? g_qh : g_kh;
                        uint32_t* dl = (which == 0) ? g_ql : g_kl;
                        dh[idx] = ph;
                        dl[idx] = pl;
                    }
                } else {
                    *(float2*)(out + (size_t)m * NC + ng) = make_float2(v0, v1);
                }
            }
        }
    }
}

// ===================== flash attention: cp.async, occ 2, bf16 3-pass =====================
static constexpr int FP = 36;
static constexpr int F_STG = 9216;
static constexpr int F_SMEM_BYTES = 2 * F_STG * 4;    // 73728

__global__ __launch_bounds__(256, 2) void flash_mma_kernel()
{
    extern __shared__ uint32_t fsm[];
    const uint32_t fsm_b = smem_u32(fsm);

    const int tid  = threadIdx.x;
    const int warp = tid >> 5, lane = tid & 31;
    const int g = lane >> 2, tq = lane & 3;
    const int qi = blockIdx.x, bh = blockIdx.y;
    const int q0 = qi * 128;
    const int rw = q0 + warp * 16 + g;

    const size_t base = (size_t)bh * NT * HP;
    const uint32_t* __restrict__ qh = g_qh + base;
    const uint32_t* __restrict__ ql = g_ql + base;
    const uint32_t* __restrict__ kh = g_kh + base;
    const uint32_t* __restrict__ kl = g_kl + base;
    const uint32_t* __restrict__ vth32 = (const uint32_t*)(const void*)g_vth
                                         + (size_t)bh * HD * (NT / 2);
    const uint32_t* __restrict__ vtl32 = (const uint32_t*)(const void*)g_vtl
                                         + (size_t)bh * HD * (NT / 2);

    auto issue = [&](int kt) {
        const uint32_t st = fsm_b + (kt & 1) * (F_STG * 4);
#pragma unroll
        for (int it = 0; it < 2; it++) {
            int c = tid + it * 256;
            int row = c >> 3, pr = (c & 7) * 4;
            uint32_t doff = (row * FP + pr) * 4;
            const size_t ksrc = (size_t)(kt * 64 + row) * HP + pr;
            cp16(st + doff,         kh + ksrc);
            cp16(st + 9216 + doff,  kl + ksrc);
            const size_t vsrc = (size_t)row * (NT / 2) + (size_t)kt * 32 + pr;
            cp16(st + 18432 + doff, vth32 + vsrc);
            cp16(st + 27648 + doff, vtl32 + vsrc);
        }
    };

    uint32_t qah[4][4], qal[4][4];
#pragma unroll
    for (int s = 0; s < 4; s++) {
        int o0 = rw * HP + s * 8 + tq;
        int o1 = (rw + 8) * HP + s * 8 + tq;
        qah[s][0] = qh[o0]; qah[s][1] = qh[o1];
        qah[s][2] = qh[o0 + 4]; qah[s][3] = qh[o1 + 4];
        qal[s][0] = ql[o0]; qal[s][1] = ql[o1];
        qal[s][2] = ql[o0 + 4]; qal[s][3] = ql[o1 + 4];
    }

    float m_i[2] = {-1e30f, -1e30f}, l_i[2] = {0.f, 0.f};
    float o[8][4] = {};

    const int nkt = 2 * qi + 2;
    issue(0); CP_COMMIT();

    for (int kt = 0; kt < nkt; kt++) {
        if (kt + 1 < nkt) {
            issue(kt + 1); CP_COMMIT();
            CP_WAIT1();
        } else {
            CP_WAIT0();
        }
        __syncthreads();

        if (q0 + warp * 16 + 15 >= kt * 64) {
            uint32_t* st = fsm + (kt & 1) * F_STG;
            const uint32_t* Ksh = st;
            const uint32_t* Ksl = st + 2304;
            const uint32_t* Vth = st + 4608;
            const uint32_t* Vtl = st + 6912;

            float s[8][4];
#pragma unroll
            for (int nt = 0; nt < 8; nt++) {
                float sa[4] = {};
#pragma unroll
                for (int ks = 0; ks < 4; ks++) {
                    int ob = (nt * 8 + g) * FP + ks * 8 + tq;
                    uint32_t bh2[2] = {Ksh[ob], Ksh[ob + 4]};
                    uint32_t bl2[2] = {Ksl[ob], Ksl[ob + 4]};
                    mma_bf16(sa, qah[ks], bl2);
                    mma_bf16(sa, qal[ks], bh2);
                    mma_bf16(sa, qah[ks], bh2);
                }
                s[nt][0] = sa[0]; s[nt][1] = sa[1]; s[nt][2] = sa[2]; s[nt][3] = sa[3];
            }

            const bool need_mask = (kt >= 2 * qi);
#pragma unroll
            for (int nt = 0; nt < 8; nt++) {
                int c0 = kt * 64 + nt * 8 + 2 * tq;
#pragma unroll
                for (int r = 0; r < 4; r++) {
                    int col = c0 + (r & 1);
                    int row = rw + (r >> 1) * 8;
                    float v = s[nt][r] * 0.125f;
                    if (need_mask && col > row) v = -1e30f;
                    s[nt][r] = v;
                }
            }

            float sc[2];
#pragma unroll
            for (int r = 0; r < 2; r++) {
                float mx = -1e30f;
#pragma unroll
                for (int nt = 0; nt < 8; nt++)
                    mx = fmaxf(mx, fmaxf(s[nt][2 * r], s[nt][2 * r + 1]));
                mx = fmaxf(mx, __shfl_xor_sync(0xffffffffu, mx, 1));
                mx = fmaxf(mx, __shfl_xor_sync(0xffffffffu, mx, 2));
                float m_new = fmaxf(m_i[r], mx);
                float sum = 0.f;
#pragma unroll
                for (int nt = 0; nt < 8; nt++) {
                    float p0 = __expf(s[nt][2 * r] - m_new);
                    float p1 = __expf(s[nt][2 * r + 1] - m_new);
                    s[nt][2 * r] = p0; s[nt][2 * r + 1] = p1;
                    sum += p0 + p1;
                }
                sum += __shfl_xor_sync(0xffffffffu, sum, 1);
                sum += __shfl_xor_sync(0xffffffffu, sum, 2);
                sc[r]  = __expf(m_i[r] - m_new);
                l_i[r] = l_i[r] * sc[r] + sum;
                m_i[r] = m_new;
            }
#pragma unroll
            for (int nt = 0; nt < 8; nt++) {
                o[nt][0] *= sc[0]; o[nt][1] *= sc[0];
                o[nt][2] *= sc[1]; o[nt][3] *= sc[1];
            }

#pragma unroll
            for (int ks = 0; ks < 4; ks++) {
                float ph[8], pl[8];
#pragma unroll
                for (int e = 0; e < 4; e++) {
                    split2(s[2 * ks][e], ph[e], pl[e]);
                    split2(s[2 * ks + 1][e], ph[4 + e], pl[4 + e]);
                }
                uint32_t pah[4] = { pack_bf16(ph[0], ph[1]), pack_bf16(ph[2], ph[3]),
                                    pack_bf16(ph[4], ph[5]), pack_bf16(ph[6], ph[7]) };
                uint32_t pal[4] = { pack_bf16(pl[0], pl[1]), pack_bf16(pl[2], pl[3]),
                                    pack_bf16(pl[4], pl[5]), pack_bf16(pl[6], pl[7]) };
#pragma unroll
                for (int nt = 0; nt < 8; nt++) {
                    int ob = (nt * 8 + g) * FP + ks * 8 + tq;
                    uint32_t bh2[2] = {Vth[ob], Vth[ob + 4]};
                    uint32_t bl2[2] = {Vtl[ob], Vtl[ob + 4]};
                    mma_bf16(o[nt], pah, bl2);
                    mma_bf16(o[nt], pal, bh2);
                    mma_bf16(o[nt], pah, bh2);
                }
            }
        }

        __syncthreads();
    }

    // ---- epilogue: write y as fp16x2 (single buffer) ----
    const int b = bh >> 4, h = bh & 15;
    float inv0 = 1.f / l_i[0], inv1 = 1.f / l_i[1];
#pragma unroll
    for (int nt = 0; nt < 8; nt++) {
        int dp = h * HP + nt * 4 + tq;
        g_y16[(size_t)(b * NT + rw) * (NC / 2) + dp] =
            pack_f16(o[nt][0] * inv0, o[nt][1] * inv0);
        g_y16[(size_t)(b * NT + rw + 8) * (NC / 2) + dp] =
            pack_f16(o[nt][2] * inv1, o[nt][3] * inv1);
    }
}

// ===========================================================================
extern "C" void kernel_launch(void* const* d_in, const int* in_sizes, int n_in,
                              void* d_out, int out_size)
{
    const float* x      = (const float*)d_in[0];
    const float* w_attn = (const float*)d_in[1];
    const float* b_attn = (const float*)d_in[2];
    const float* w_proj = (const float*)d_in[3];
    const float* b_proj = (const float*)d_in[4];
    float* out = (float*)d_out;

    cudaFuncSetAttribute(gemm_f16_kernel<0>,
                         cudaFuncAttributeMaxDynamicSharedMemorySize, G_SMEM_BYTES);
    cudaFuncSetAttribute(gemm_f16_kernel<1>,
                         cudaFuncAttributeMaxDynamicSharedMemorySize, G_SMEM_BYTES);
    cudaFuncSetAttribute(flash_mma_kernel,
                         cudaFuncAttributeMaxDynamicSharedMemorySize, F_SMEM_BYTES);

    // pre-split passes
    {
        uint32_t *x16, *wah, *wal, *wph, *wpl;
        cudaGetSymbolAddress((void**)&x16, g_x16);
        cudaGetSymbolAddress((void**)&wah, g_wa16h);
        cudaGetSymbolAddress((void**)&wal, g_wa16l);
        cudaGetSymbolAddress((void**)&wph, g_wp16h);
        cudaGetSymbolAddress((void**)&wpl, g_wp16l);
        const int npx = NB * NT * NC / 2;
        split_x16_kernel<<<(npx + 255) / 256, 256>>>(x, x16, npx);
        split_wT16_kernel<3 * NC><<<dim3(3 * NC / 64, NC / 32), 256>>>(w_attn, wah, wal);
        split_wT16_kernel<NC><<<dim3(NC / 64, NC / 32), 256>>>(w_proj, wph, wpl);
    }

    dim3 g1(3 * NC / BN, (NB * NT) / BM);   // (24, 64)
    gemm_f16_kernel<0><<<g1, 256, G_SMEM_BYTES>>>(b_attn, nullptr);

    dim3 g2(NT / 128, NB * NHH);            // (16, 64)
    flash_mma_kernel<<<g2, 256, F_SMEM_BYTES>>>();

    dim3 g3(NC / BN, (NB * NT) / BM);       // (8, 64)
    gemm_f16_kernel<1><<<g3, 256, G_SMEM_BYTES>>>(b_proj, out);
}